// round 10
// baseline (speedup 1.0000x reference)
#include <cuda_runtime.h>
#include <cuda_fp16.h>
#include <cstdint>

// Problem constants
#define NN   64
#define DD   512
#define TT   256
#define QQ   6
#define CC   1024
#define NT   (NN*TT)              // 16384
#define OUT_QUANT   (NN*DD*TT)    // 8388608
#define OUT_IDX     (NT*QQ)       // 98304

// Scratch (device globals — no runtime allocation allowed)
__device__ __half g_res_h[(size_t)NT * DD];     // residual hi (fp16)
__device__ __half g_res_l[(size_t)NT * DD];     // residual lo (fp16)
__device__ __half g_cb_h[(size_t)QQ * CC * DD]; // codebook hi
__device__ __half g_cb_l[(size_t)QQ * CC * DD]; // codebook lo
__device__ float  g_cbnorm[QQ * CC];            // ||c||^2 per code per stage
__device__ int    g_indices[NT * QQ];
__device__ unsigned long long g_best[NT];       // packed (dist,code)
__device__ int    g_hist2[QQ * CC];             // per-stage histograms
__device__ float  g_loss[QQ];

// ===========================================================================
// helpers
// ===========================================================================
__device__ __forceinline__ uint32_t smem_u32(const void* p) {
    uint32_t a;
    asm("{ .reg .u64 t; cvta.to.shared.u64 t, %1; cvt.u32.u64 %0, t; }" : "=r"(a) : "l"(p));
    return a;
}
__device__ __forceinline__ uint32_t swz(uint32_t off) {           // Swizzle<3,4,3>
    return off ^ ((off >> 3) & 0x70);
}
__device__ __forceinline__ unsigned int sortable_f32(float f) {
    unsigned int u = __float_as_uint(f);
    return (u & 0x80000000u) ? ~u : (u | 0x80000000u);
}

#define CP16(dst, src) \
    asm volatile("cp.async.ca.shared.global [%0], [%1], 16;" :: "r"(dst), "l"(src))
#define CP_COMMIT() asm volatile("cp.async.commit_group;" ::: "memory")
#define CP_WAIT0()  asm volatile("cp.async.wait_group 0;" ::: "memory")

__device__ __forceinline__ void ldsm_x4(uint32_t* r, uint32_t addr) {
    asm volatile("ldmatrix.sync.aligned.m8n8.x4.shared.b16 {%0,%1,%2,%3}, [%4];"
        : "=r"(r[0]), "=r"(r[1]), "=r"(r[2]), "=r"(r[3]) : "r"(addr));
}
__device__ __forceinline__ void mma_16816(float* d, const uint32_t* a,
                                          uint32_t b0, uint32_t b1) {
    asm volatile(
        "mma.sync.aligned.m16n8k16.row.col.f32.f16.f16.f32 "
        "{%0,%1,%2,%3}, {%4,%5,%6,%7}, {%8,%9}, {%0,%1,%2,%3};"
        : "+f"(d[0]), "+f"(d[1]), "+f"(d[2]), "+f"(d[3])
        : "r"(a[0]), "r"(a[1]), "r"(a[2]), "r"(a[3]), "r"(b0), "r"(b1));
}

// ===========================================================================
// init: zero hist2 + loss, set g_best to +inf keys (graph replays)
// ===========================================================================
__global__ void init_kernel() {
    int i = blockIdx.x * blockDim.x + threadIdx.x;   // grid 64 x 256 = 16384
    if (i < NT) g_best[i] = 0xFFFFFFFFFFFFFFFFull;
    if (i < QQ * CC) g_hist2[i] = 0;
    if (i < QQ) g_loss[i] = 0.0f;
}

// codebook prep: split fp32 -> (hi, lo) fp16 AND compute ||c||^2; one block/code
__global__ void cbprep_kernel(const float* __restrict__ cb) {
    int code = blockIdx.x;             // 0..6143 (q*1024+c)
    int tid  = threadIdx.x;            // 128
    size_t base = (size_t)code * DD;
    float4 v = ((const float4*)(cb + base))[tid];

    __half hx = __float2half(v.x), hy = __float2half(v.y);
    __half hz = __float2half(v.z), hw = __float2half(v.w);
    __half2* hp = (__half2*)(g_cb_h + base + tid * 4);
    __half2* lp = (__half2*)(g_cb_l + base + tid * 4);
    hp[0] = __halves2half2(hx, hy); hp[1] = __halves2half2(hz, hw);
    lp[0] = __halves2half2(__float2half(v.x - __half2float(hx)),
                           __float2half(v.y - __half2float(hy)));
    lp[1] = __halves2half2(__float2half(v.z - __half2float(hz)),
                           __float2half(v.w - __half2float(hw)));

    float s = v.x * v.x + v.y * v.y + v.z * v.z + v.w * v.w;
    #pragma unroll
    for (int off = 16; off > 0; off >>= 1) s += __shfl_down_sync(0xffffffffu, s, off);
    __shared__ float ws[4];
    if ((tid & 31) == 0) ws[tid >> 5] = s;
    __syncthreads();
    if (tid == 0) g_cbnorm[code] = ws[0] + ws[1] + ws[2] + ws[3];
}

// transpose in: x (N, D, T) -> residual (NT, D) as fp16 hi/lo
__global__ void transpose_in_kernel(const float* __restrict__ x) {
    __shared__ float tile[32][33];
    int n  = blockIdx.z;
    int t0 = blockIdx.x * 32;
    int d0 = blockIdx.y * 32;
    int tx = threadIdx.x, ty = threadIdx.y;  // (32, 8)

    #pragma unroll
    for (int i = 0; i < 4; i++) {
        int d = d0 + ty + i * 8;
        tile[ty + i * 8][tx] = x[(size_t)n * DD * TT + (size_t)d * TT + (t0 + tx)];
    }
    __syncthreads();
    #pragma unroll
    for (int i = 0; i < 4; i++) {
        int t = t0 + ty + i * 8;
        float v = tile[tx][ty + i * 8];
        size_t gi = (size_t)(n * TT + t) * DD + (d0 + tx);
        __half h = __float2half(v);
        g_res_h[gi] = h;
        g_res_l[gi] = __float2half(v - __half2float(h));
    }
}

// ===========================================================================
// persistent mma.sync argmin: grid = 304 CTAs, each loops over tiles
// (tile = 64 rows x 128 codes x K512; 2048 tiles). 128 threads = 4 warps
// (2m x 2n), warp tile 32x64 (2x8 m16n8k16 frags). fp16 2-split
// (hh + hl + lh), fp32 accum. TERM-MAJOR MMA ordering: all 16 hh, then all
// 16 hl, then all 16 lh per k-step -> every accumulator's dependent MMAs
// are 16 issues apart (RAW chain hidden).
// ===========================================================================
#define MROWS   64
#define NCODES  128
#define KC      64                  // halves per chunk (128 B rows)
#define NCHUNK  (DD / KC)           // 8
#define NTILES  ((NT / MROWS) * (CC / NCODES))   // 256 * 8 = 2048
#define GRID_ARG 304                // 2 x 152 SMs

// dynamic smem layout
#define OFF_BUF  1024
#define OFF_AH   0
#define OFF_AL   (8*1024)
#define OFF_BH   (16*1024)
#define OFF_BL   (32*1024)
#define BUF_BYTES (48*1024)
#define ARG_SMEM (OFF_BUF + 2*BUF_BYTES)   // 99328

__global__ void __launch_bounds__(128) argmin_kernel(int q) {
    extern __shared__ char smem[];
    unsigned long long* s_best = (unsigned long long*)smem;
    const uint32_t sb = smem_u32(smem);
    const int tid  = threadIdx.x;
    const int lane = tid & 31;
    const int wid  = tid >> 5;
    const int wm   = wid & 1;          // 0..1  (32 rows each)
    const int wn   = wid >> 1;         // 0..1  (64 codes each)
    const int bid  = blockIdx.x;

    const __half* __restrict__ resh = g_res_h;
    const __half* __restrict__ resl = g_res_l;
    const __half* __restrict__ cbh  = g_cb_h + (size_t)q * CC * DD;
    const __half* __restrict__ cbl  = g_cb_l + (size_t)q * CC * DD;
    const float*  __restrict__ norms = g_cbnorm + q * CC;

    if (tid < MROWS) s_best[tid] = 0xFFFFFFFFFFFFFFFFull;

    // how many tiles this CTA owns: tiles t = bid + GRID_ARG*j < NTILES
    int ntiles = 0;
    for (int t = bid; t < NTILES; t += GRID_ARG) ntiles++;
    if (ntiles == 0) return;
    const int NG = ntiles * NCHUNK;

    float d[2][8][4];

    // ldmatrix lane-address components
    const int aRow  = (lane & 7) + ((lane >> 3) & 1) * 8;
    const int aK    = ((lane >> 4) & 1) * 8;
    const int bCode = (lane & 7) + ((lane >> 4) & 1) * 8;
    const int bK    = ((lane >> 3) & 1) * 8;

    auto issue = [&](int g) {
        const int t  = bid + GRID_ARG * (g >> 3);          // tile index
        const int rb = (t & 255) * MROWS;                  // row base
        const int ct = (t >> 8) * NCODES;                  // code base
        const int k0 = (g & 7) * KC;
        const uint32_t bufb = sb + OFF_BUF + (g & 1) * BUF_BYTES;
        #pragma unroll
        for (int p = 0; p < 4; p++) {
            int seg = tid + p * 128;         // 0..511
            int row = seg >> 3, s8 = seg & 7;
            uint32_t so = swz((uint32_t)(row * 128 + s8 * 16));
            const size_t gi = (size_t)(rb + row) * DD + k0 + s8 * 8;
            CP16(bufb + OFF_AH + so, resh + gi);
            CP16(bufb + OFF_AL + so, resl + gi);
        }
        #pragma unroll
        for (int p = 0; p < 8; p++) {
            int seg = tid + p * 128;         // 0..1023
            int row = seg >> 3, s8 = seg & 7;
            uint32_t so = swz((uint32_t)(row * 128 + s8 * 16));
            const size_t gi = (size_t)(ct + row) * DD + k0 + s8 * 8;
            CP16(bufb + OFF_BH + so, cbh + gi);
            CP16(bufb + OFF_BL + so, cbl + gi);
        }
        CP_COMMIT();
    };

    issue(0);
    for (int g = 0; g < NG; g++) {
        CP_WAIT0();            // buffer (g&1) holds chunk g
        __syncthreads();       // publish loads; all done computing buffer (g+1)&1

        // tile-boundary: merge previous tile's s_best to global, reset, zero acc
        if ((g & 7) == 0) {
            if (g > 0) {
                const int tprev = bid + GRID_ARG * ((g >> 3) - 1);
                const int rbPrev = (tprev & 255) * MROWS;
                if (tid < MROWS) {
                    atomicMin(&g_best[rbPrev + tid], s_best[tid]);
                    s_best[tid] = 0xFFFFFFFFFFFFFFFFull;
                }
            }
            #pragma unroll
            for (int i = 0; i < 2; i++)
                #pragma unroll
                for (int j = 0; j < 8; j++)
                    #pragma unroll
                    for (int e = 0; e < 4; e++) d[i][j][e] = 0.0f;
        }

        if (g + 1 < NG) issue(g + 1);   // safe: sync above released that buffer

        const uint32_t bufb = sb + OFF_BUF + (g & 1) * BUF_BYTES;
        #pragma unroll
        for (int kk = 0; kk < KC; kk += 16) {
            // ---- load ALL fragments for this k-step ----
            uint32_t ah[2][4], al[2][4];
            uint32_t bh[4][4], bl[4][4];
            #pragma unroll
            for (int i = 0; i < 2; i++) {
                uint32_t so = swz((uint32_t)((wm * 32 + i * 16 + aRow) * 128 + (kk + aK) * 2));
                ldsm_x4(ah[i], bufb + OFF_AH + so);
                ldsm_x4(al[i], bufb + OFF_AL + so);
            }
            #pragma unroll
            for (int j2 = 0; j2 < 4; j2++) {
                uint32_t so = swz((uint32_t)((wn * 64 + j2 * 16 + bCode) * 128 + (kk + bK) * 2));
                ldsm_x4(bh[j2], bufb + OFF_BH + so);
                ldsm_x4(bl[j2], bufb + OFF_BL + so);
            }
            // ---- term-major MMA issue: 16 independent per pass ----
            #pragma unroll
            for (int j2 = 0; j2 < 4; j2++)
                #pragma unroll
                for (int i = 0; i < 2; i++)
                    #pragma unroll
                    for (int h = 0; h < 2; h++)
                        mma_16816(d[i][j2 * 2 + h], ah[i], bh[j2][h * 2], bh[j2][h * 2 + 1]); // hh
            #pragma unroll
            for (int j2 = 0; j2 < 4; j2++)
                #pragma unroll
                for (int i = 0; i < 2; i++)
                    #pragma unroll
                    for (int h = 0; h < 2; h++)
                        mma_16816(d[i][j2 * 2 + h], ah[i], bl[j2][h * 2], bl[j2][h * 2 + 1]); // hl
            #pragma unroll
            for (int j2 = 0; j2 < 4; j2++)
                #pragma unroll
                for (int i = 0; i < 2; i++)
                    #pragma unroll
                    for (int h = 0; h < 2; h++)
                        mma_16816(d[i][j2 * 2 + h], al[i], bh[j2][h * 2], bh[j2][h * 2 + 1]); // lh
        }

        // ---- tile epilogue: fold distances into s_best ----
        if ((g & 7) == 7) {
            const int t  = bid + GRID_ARG * (g >> 3);
            const int ct = (t >> 8) * NCODES;
            float bV[4];
            int   bI[4];
            #pragma unroll
            for (int s = 0; s < 4; s++) { bV[s] = 3.4e38f; bI[s] = 0; }
            #pragma unroll
            for (int i = 0; i < 2; i++)
                #pragma unroll
                for (int j = 0; j < 8; j++)
                    #pragma unroll
                    for (int e = 0; e < 4; e++) {
                        int col = ct + wn * 64 + j * 8 + 2 * (lane & 3) + (e & 1);
                        float dist = __ldg(&norms[col]) - 2.0f * d[i][j][e];
                        int s = i * 2 + (e >> 1);
                        if (dist < bV[s]) { bV[s] = dist; bI[s] = col; }
                    }
            #pragma unroll
            for (int s = 0; s < 4; s++) {
                float v = bV[s];
                int   b = bI[s];
                #pragma unroll
                for (int off = 1; off < 4; off <<= 1) {
                    float ov = __shfl_xor_sync(0xffffffffu, v, off);
                    int   ob = __shfl_xor_sync(0xffffffffu, b, off);
                    if (ov < v || (ov == v && ob < b)) { v = ov; b = ob; }
                }
                if ((lane & 3) == 0) {
                    int rowL = wm * 32 + (s >> 1) * 16 + (lane >> 2) + (s & 1) * 8;
                    unsigned long long key =
                        ((unsigned long long)sortable_f32(v) << 32) | (unsigned int)b;
                    atomicMin(&s_best[rowL], key);
                }
            }
        }
    }

    // final tile's merge
    __syncthreads();
    {
        const int tlast = bid + GRID_ARG * (ntiles - 1);
        const int rbLast = (tlast & 255) * MROWS;
        if (tid < MROWS) atomicMin(&g_best[rbLast + tid], s_best[tid]);
    }
}

// ===========================================================================
// residual update: res(h,l) -= cb[idx]; commitment loss; histogram; index
// extract; reset g_best for the next stage. 2 rows per block, 256 threads.
// ===========================================================================
__global__ void __launch_bounds__(256) update_kernel(const float* __restrict__ cb, int q) {
    const int tid = threadIdx.x;
    const int sub = tid >> 7;            // row within block (0/1)
    const int t   = tid & 127;           // 128 threads per row
    const int row = blockIdx.x * 2 + sub;

    const int c = (int)(unsigned int)(g_best[row] & 0xFFFFFFFFull);
    __syncthreads();                     // all reads of g_best before reset
    if (t == 0) {
        g_indices[row * QQ + q] = c;
        atomicAdd(&g_hist2[q * CC + c], 1);
        g_best[row] = 0xFFFFFFFFFFFFFFFFull;   // ready for next stage / launch
    }

    const size_t base = (size_t)row * DD + t * 4;
    __half2* hp = (__half2*)(g_res_h + base);
    __half2* lp = (__half2*)(g_res_l + base);
    __half2 h0 = hp[0], h1 = hp[1], l0 = lp[0], l1 = lp[1];
    float4 cv = *(const float4*)(cb + (size_t)c * DD + t * 4);

    float r0 = (__low2float(h0)  + __low2float(l0))  - cv.x;
    float r1 = (__high2float(h0) + __high2float(l0)) - cv.y;
    float r2 = (__low2float(h1)  + __low2float(l1))  - cv.z;
    float r3 = (__high2float(h1) + __high2float(l1)) - cv.w;

    __half a0 = __float2half(r0), a1 = __float2half(r1);
    __half a2 = __float2half(r2), a3 = __float2half(r3);
    hp[0] = __halves2half2(a0, a1);
    hp[1] = __halves2half2(a2, a3);
    lp[0] = __halves2half2(__float2half(r0 - __half2float(a0)),
                           __float2half(r1 - __half2float(a1)));
    lp[1] = __halves2half2(__float2half(r2 - __half2float(a2)),
                           __float2half(r3 - __half2float(a3)));

    float s = r0 * r0 + r1 * r1 + r2 * r2 + r3 * r3;
    #pragma unroll
    for (int off = 16; off > 0; off >>= 1) s += __shfl_down_sync(0xffffffffu, s, off);
    __shared__ float ws[8];
    if ((tid & 31) == 0) ws[tid >> 5] = s;
    __syncthreads();
    if (tid == 0) {
        float tot = 0.0f;
        #pragma unroll
        for (int i = 0; i < 8; i++) tot += ws[i];
        atomicAdd(&g_loss[q], tot);
    }
}

// ---------------------------------------------------------------------------
// output: quantized_out (N,D,T) = x - residual_final  (transpose back)
// ---------------------------------------------------------------------------
__global__ void transpose_out_kernel(const float* __restrict__ x, float* __restrict__ out) {
    __shared__ float tile[32][33];
    int n  = blockIdx.z;
    int t0 = blockIdx.x * 32;
    int d0 = blockIdx.y * 32;
    int tx = threadIdx.x, ty = threadIdx.y;  // (32, 8)

    #pragma unroll
    for (int i = 0; i < 4; i++) {
        int t = t0 + ty + i * 8;
        size_t gi = (size_t)(n * TT + t) * DD + (d0 + tx);
        tile[ty + i * 8][tx] = __half2float(g_res_h[gi]) + __half2float(g_res_l[gi]);
    }
    __syncthreads();
    #pragma unroll
    for (int i = 0; i < 4; i++) {
        int d = d0 + ty + i * 8;
        size_t gi = (size_t)n * DD * TT + (size_t)d * TT + (t0 + tx);
        out[gi] = x[gi] - tile[tx][ty + i * 8];
    }
}

__global__ void idx_kernel(float* __restrict__ out) {
    int i = blockIdx.x * blockDim.x + threadIdx.x;
    if (i < OUT_IDX) out[OUT_QUANT + i] = (float)g_indices[i];
}

// all 6 perplexities + mean loss in one kernel
__global__ void finalize_kernel(float* __restrict__ out) {
    int tid = threadIdx.x;   // 256
    __shared__ float ws[8];
    __shared__ float perp_sum;
    if (tid == 0) perp_sum = 0.0f;
    __syncthreads();

    for (int q = 0; q < QQ; q++) {
        float s = 0.0f;
        for (int i = tid; i < CC; i += 256) {
            float p = (float)g_hist2[q * CC + i] * (1.0f / (float)NT);
            s += p * logf(p + 1e-10f);
        }
        #pragma unroll
        for (int off = 16; off > 0; off >>= 1) s += __shfl_down_sync(0xffffffffu, s, off);
        if ((tid & 31) == 0) ws[tid >> 5] = s;
        __syncthreads();
        if (tid == 0) {
            float t = 0.0f;
            #pragma unroll
            for (int i = 0; i < 8; i++) t += ws[i];
            perp_sum += expf(-t);
        }
        __syncthreads();
    }

    if (tid == 0) {
        float l = 0.0f;
        #pragma unroll
        for (int q = 0; q < QQ; q++) l += g_loss[q];
        out[OUT_QUANT + OUT_IDX + 0] = l / ((float)NT * (float)DD) / (float)QQ;
        out[OUT_QUANT + OUT_IDX + 1] = perp_sum / (float)QQ;
    }
}

// ---------------------------------------------------------------------------
extern "C" void kernel_launch(void* const* d_in, const int* in_sizes, int n_in,
                              void* d_out, int out_size) {
    const float* x  = (const float*)d_in[0];   // (64, 512, 256) fp32
    const float* cb = (const float*)d_in[1];   // (6, 1024, 512) fp32
    float* out = (float*)d_out;

    static bool attr_set = false;
    if (!attr_set) {
        cudaFuncSetAttribute(argmin_kernel,
                             cudaFuncAttributeMaxDynamicSharedMemorySize, ARG_SMEM);
        attr_set = true;
    }

    init_kernel<<<64, 256>>>();

    dim3 tb(32, 8);
    dim3 tg(TT / 32, DD / 32, NN);   // (8, 16, 64)
    transpose_in_kernel<<<tg, tb>>>(x);

    cbprep_kernel<<<QQ * CC, 128>>>(cb);

    for (int q = 0; q < QQ; q++) {
        const float* cbq = cb + (size_t)q * CC * DD;
        argmin_kernel<<<GRID_ARG, 128, ARG_SMEM>>>(q);
        update_kernel<<<NT / 2, 256>>>(cbq, q);
    }

    transpose_out_kernel<<<tg, tb>>>(x, out);
    idx_kernel<<<(OUT_IDX + 255) / 256, 256>>>(out);
    finalize_kernel<<<1, 256>>>(out);
}

// round 11
// speedup vs baseline: 1.2660x; 1.2660x over previous
#include <cuda_runtime.h>
#include <cuda_fp16.h>
#include <cstdint>

// Problem constants
#define NN   64
#define DD   512
#define TT   256
#define QQ   6
#define CC   1024
#define NT   (NN*TT)              // 16384
#define OUT_QUANT   (NN*DD*TT)    // 8388608
#define OUT_IDX     (NT*QQ)       // 98304

// Scratch (device globals — no runtime allocation allowed)
__device__ __half g_res_h[(size_t)NT * DD];     // residual hi (fp16)
__device__ __half g_res_l[(size_t)NT * DD];     // residual lo (fp16)
__device__ __half g_cb_h[(size_t)QQ * CC * DD]; // codebook hi
__device__ float  g_cbnorm[QQ * CC];            // ||c||^2 per code per stage
__device__ float  g_dist[(size_t)NT * CC];      // hh-approx distances (67MB)
__device__ float  g_rnorm2[NT];                 // ||residual_row||^2
__device__ int    g_cmax2[QQ];                  // max ||c||^2 per stage (float bits)
__device__ int    g_indices[NT * QQ];
__device__ int    g_hist2[QQ * CC];             // per-stage histograms
__device__ float  g_loss[QQ];

// ===========================================================================
// helpers
// ===========================================================================
__device__ __forceinline__ uint32_t smem_u32(const void* p) {
    uint32_t a;
    asm("{ .reg .u64 t; cvta.to.shared.u64 t, %1; cvt.u32.u64 %0, t; }" : "=r"(a) : "l"(p));
    return a;
}
__device__ __forceinline__ uint32_t swz(uint32_t off) {           // Swizzle<3,4,3>
    return off ^ ((off >> 3) & 0x70);
}
__device__ __forceinline__ unsigned int sortable_f32(float f) {
    unsigned int u = __float_as_uint(f);
    return (u & 0x80000000u) ? ~u : (u | 0x80000000u);
}

#define CP16(dst, src) \
    asm volatile("cp.async.ca.shared.global [%0], [%1], 16;" :: "r"(dst), "l"(src))
#define CP_COMMIT() asm volatile("cp.async.commit_group;" ::: "memory")
#define CP_WAIT0()  asm volatile("cp.async.wait_group 0;" ::: "memory")

__device__ __forceinline__ void ldsm_x4(uint32_t* r, uint32_t addr) {
    asm volatile("ldmatrix.sync.aligned.m8n8.x4.shared.b16 {%0,%1,%2,%3}, [%4];"
        : "=r"(r[0]), "=r"(r[1]), "=r"(r[2]), "=r"(r[3]) : "r"(addr));
}
__device__ __forceinline__ void mma_16816(float* d, const uint32_t* a,
                                          uint32_t b0, uint32_t b1) {
    asm volatile(
        "mma.sync.aligned.m16n8k16.row.col.f32.f16.f16.f32 "
        "{%0,%1,%2,%3}, {%4,%5,%6,%7}, {%8,%9}, {%0,%1,%2,%3};"
        : "+f"(d[0]), "+f"(d[1]), "+f"(d[2]), "+f"(d[3])
        : "r"(a[0]), "r"(a[1]), "r"(a[2]), "r"(a[3]), "r"(b0), "r"(b1));
}

// ===========================================================================
// init: zero hist2 + loss + rnorm2 + cmax (graph replays)
// ===========================================================================
__global__ void init_kernel() {
    int i = blockIdx.x * blockDim.x + threadIdx.x;   // grid 64 x 256 = 16384
    if (i < NT) g_rnorm2[i] = 0.0f;
    if (i < QQ * CC) g_hist2[i] = 0;
    if (i < QQ) { g_loss[i] = 0.0f; g_cmax2[i] = 0; }
}

// codebook prep: hi split, ||c||^2, per-stage max norm
__global__ void cbprep_kernel(const float* __restrict__ cb) {
    int code = blockIdx.x;             // 0..6143 (q*1024+c)
    int tid  = threadIdx.x;            // 128
    size_t base = (size_t)code * DD;
    float4 v = ((const float4*)(cb + base))[tid];

    __half2* hp = (__half2*)(g_cb_h + base + tid * 4);
    hp[0] = __halves2half2(__float2half(v.x), __float2half(v.y));
    hp[1] = __halves2half2(__float2half(v.z), __float2half(v.w));

    float s = v.x * v.x + v.y * v.y + v.z * v.z + v.w * v.w;
    #pragma unroll
    for (int off = 16; off > 0; off >>= 1) s += __shfl_down_sync(0xffffffffu, s, off);
    __shared__ float ws[4];
    if ((tid & 31) == 0) ws[tid >> 5] = s;
    __syncthreads();
    if (tid == 0) {
        float n = ws[0] + ws[1] + ws[2] + ws[3];
        g_cbnorm[code] = n;
        atomicMax(&g_cmax2[code >> 10], __float_as_int(n));  // norms > 0
    }
}

// transpose in: x (N, D, T) -> residual (NT, D) fp16 hi/lo; accumulate row norms
__global__ void transpose_in_kernel(const float* __restrict__ x) {
    __shared__ float tile[32][33];
    int n  = blockIdx.z;
    int t0 = blockIdx.x * 32;
    int d0 = blockIdx.y * 32;
    int tx = threadIdx.x, ty = threadIdx.y;  // (32, 8)

    #pragma unroll
    for (int i = 0; i < 4; i++) {
        int d = d0 + ty + i * 8;
        tile[ty + i * 8][tx] = x[(size_t)n * DD * TT + (size_t)d * TT + (t0 + tx)];
    }
    __syncthreads();
    #pragma unroll
    for (int i = 0; i < 4; i++) {
        int t = t0 + ty + i * 8;
        float v = tile[tx][ty + i * 8];
        size_t gi = (size_t)(n * TT + t) * DD + (d0 + tx);
        __half h = __float2half(v);
        g_res_h[gi] = h;
        g_res_l[gi] = __float2half(v - __half2float(h));
        // warp-reduce v^2 across tx (one warp per (ty,i) row), one atomic per warp
        float s = v * v;
        #pragma unroll
        for (int off = 16; off > 0; off >>= 1) s += __shfl_down_sync(0xffffffffu, s, off);
        if (tx == 0) atomicAdd(&g_rnorm2[n * TT + t], s);
    }
}

// ===========================================================================
// PASS 1: hh-only distance matrix. Persistent grid, tile = 64 rows x 128
// codes x K512, 128 threads = 4 warps (2m x 2n), 8 MMAs per k16.
// Writes d_hh = ||c||^2 - 2*(a_h . b_h) to g_dist.
// ===========================================================================
#define MROWS   64
#define NCODES  128
#define KC      64
#define NCHUNK  (DD / KC)           // 8
#define NTILES  ((NT / MROWS) * (CC / NCODES))   // 2048
#define GRID_ARG 456

#define OFF_BUF  0
#define OFF_AH   0
#define OFF_BH   (8*1024)
#define BUF_BYTES (24*1024)
#define ARG_SMEM (2*BUF_BYTES)      // 49152

__global__ void __launch_bounds__(128) dist_kernel(int q) {
    extern __shared__ char smem[];
    const uint32_t sb = smem_u32(smem);
    const int tid  = threadIdx.x;
    const int lane = tid & 31;
    const int wid  = tid >> 5;
    const int wm   = wid & 1;          // 0..1  (32 rows each)
    const int wn   = wid >> 1;         // 0..1  (64 codes each)
    const int bid  = blockIdx.x;

    const __half* __restrict__ resh = g_res_h;
    const __half* __restrict__ cbh  = g_cb_h + (size_t)q * CC * DD;
    const float*  __restrict__ norms = g_cbnorm + q * CC;

    int ntiles = 0;
    for (int t = bid; t < NTILES; t += GRID_ARG) ntiles++;
    if (ntiles == 0) return;
    const int NG = ntiles * NCHUNK;

    float d[2][8][4];

    const int aRow  = (lane & 7) + ((lane >> 3) & 1) * 8;
    const int aK    = ((lane >> 4) & 1) * 8;
    const int bCode = (lane & 7) + ((lane >> 4) & 1) * 8;
    const int bK    = ((lane >> 3) & 1) * 8;

    auto issue = [&](int g) {
        const int t  = bid + GRID_ARG * (g >> 3);
        const int rb = (t & 255) * MROWS;
        const int ct = (t >> 8) * NCODES;
        const int k0 = (g & 7) * KC;
        const uint32_t bufb = sb + (g & 1) * BUF_BYTES;
        #pragma unroll
        for (int p = 0; p < 4; p++) {
            int seg = tid + p * 128;         // 0..511 (A: 64 rows x 8 segs)
            int row = seg >> 3, s8 = seg & 7;
            uint32_t so = swz((uint32_t)(row * 128 + s8 * 16));
            CP16(bufb + OFF_AH + so, resh + (size_t)(rb + row) * DD + k0 + s8 * 8);
        }
        #pragma unroll
        for (int p = 0; p < 8; p++) {
            int seg = tid + p * 128;         // 0..1023 (B: 128 codes x 8 segs)
            int row = seg >> 3, s8 = seg & 7;
            uint32_t so = swz((uint32_t)(row * 128 + s8 * 16));
            CP16(bufb + OFF_BH + so, cbh + (size_t)(ct + row) * DD + k0 + s8 * 8);
        }
        CP_COMMIT();
    };

    issue(0);
    for (int g = 0; g < NG; g++) {
        CP_WAIT0();
        __syncthreads();

        if ((g & 7) == 0) {
            #pragma unroll
            for (int i = 0; i < 2; i++)
                #pragma unroll
                for (int j = 0; j < 8; j++)
                    #pragma unroll
                    for (int e = 0; e < 4; e++) d[i][j][e] = 0.0f;
        }

        if (g + 1 < NG) issue(g + 1);

        const uint32_t bufb = sb + (g & 1) * BUF_BYTES;
        #pragma unroll
        for (int kk = 0; kk < KC; kk += 16) {
            uint32_t ah[2][4];
            #pragma unroll
            for (int i = 0; i < 2; i++) {
                uint32_t so = swz((uint32_t)((wm * 32 + i * 16 + aRow) * 128 + (kk + aK) * 2));
                ldsm_x4(ah[i], bufb + OFF_AH + so);
            }
            #pragma unroll
            for (int j2 = 0; j2 < 4; j2++) {
                uint32_t bh[4];
                uint32_t so = swz((uint32_t)((wn * 64 + j2 * 16 + bCode) * 128 + (kk + bK) * 2));
                ldsm_x4(bh, bufb + OFF_BH + so);
                #pragma unroll
                for (int i = 0; i < 2; i++)
                    #pragma unroll
                    for (int h = 0; h < 2; h++)
                        mma_16816(d[i][j2 * 2 + h], ah[i], bh[h * 2], bh[h * 2 + 1]);
            }
        }

        // tile epilogue: write d_hh
        if ((g & 7) == 7) {
            const int t  = bid + GRID_ARG * (g >> 3);
            const int rb = (t & 255) * MROWS;
            const int ct = (t >> 8) * NCODES;
            #pragma unroll
            for (int i = 0; i < 2; i++)
                #pragma unroll
                for (int j = 0; j < 8; j++)
                    #pragma unroll
                    for (int e = 0; e < 4; e++) {
                        int row = rb + wm * 32 + i * 16 + (lane >> 2) + (e >> 1) * 8;
                        int col = ct + wn * 64 + j * 8 + 2 * (lane & 3) + (e & 1);
                        g_dist[(size_t)row * CC + col] = norms[col] - 2.0f * d[i][j][e];
                    }
        }
    }
}

// ===========================================================================
// PASS 2: per-row candidate refine + residual update + loss + histogram.
// One block per row, 256 threads.
// ===========================================================================
__global__ void __launch_bounds__(256) refine_update_kernel(const float* __restrict__ cb32, int q) {
    const int row = blockIdx.x;
    const int tid = threadIdx.x;
    __shared__ float s_a[DD];                 // exact residual (h+l), 2KB
    __shared__ unsigned long long s_red[8];
    __shared__ float s_fred[8];
    __shared__ int s_list[128];
    __shared__ int s_cnt;
    __shared__ int s_bestc;
    __shared__ float s_dmin;

    const float* __restrict__ norms = g_cbnorm + q * CC;

    // reconstruct exact residual row
    #pragma unroll
    for (int k = tid; k < DD; k += 256) {
        size_t gi = (size_t)row * DD + k;
        s_a[k] = __half2float(g_res_h[gi]) + __half2float(g_res_l[gi]);
    }
    if (tid == 0) s_cnt = 0;

    // load d_hh (4 per thread) + local argmin (ascending index)
    float4 dv = *(const float4*)(g_dist + (size_t)row * CC + tid * 4);
    float bv = dv.x; int bi = tid * 4;
    if (dv.y < bv) { bv = dv.y; bi = tid * 4 + 1; }
    if (dv.z < bv) { bv = dv.z; bi = tid * 4 + 2; }
    if (dv.w < bv) { bv = dv.w; bi = tid * 4 + 3; }
    unsigned long long key = ((unsigned long long)sortable_f32(bv) << 32) | (unsigned)bi;
    #pragma unroll
    for (int off = 16; off > 0; off >>= 1) {
        unsigned long long o = __shfl_down_sync(0xffffffffu, key, off);
        if (o < key) key = o;
    }
    if ((tid & 31) == 0) s_red[tid >> 5] = key;
    __syncthreads();
    if (tid == 0) {
        unsigned long long k0 = s_red[0];
        #pragma unroll
        for (int i = 1; i < 8; i++) if (s_red[i] < k0) k0 = s_red[i];
        unsigned u = (unsigned)(k0 >> 32);
        s_dmin = __uint_as_float((u & 0x80000000u) ? (u & 0x7FFFFFFFu) : ~u);
    }
    __syncthreads();

    // margin: |d_exact - d_hh| <= 2^-9 * ||a|| * ||c||; pairwise 2^-8; x2 safety
    float cmax = sqrtf(__int_as_float(g_cmax2[q]));
    float eps  = sqrtf(g_rnorm2[row]) * cmax * (1.0f / 128.0f) + 1e-3f;
    float T = s_dmin + eps;

    int base = tid * 4;
    if (dv.x <= T) { int p = atomicAdd(&s_cnt, 1); if (p < 128) s_list[p] = base; }
    if (dv.y <= T) { int p = atomicAdd(&s_cnt, 1); if (p < 128) s_list[p] = base + 1; }
    if (dv.z <= T) { int p = atomicAdd(&s_cnt, 1); if (p < 128) s_list[p] = base + 2; }
    if (dv.w <= T) { int p = atomicAdd(&s_cnt, 1); if (p < 128) s_list[p] = base + 3; }
    __syncthreads();
    int nc = min(s_cnt, 128);

    // exact fp32 refinement over candidates
    float bestd = 3.4e38f;
    int   bestc = CC;
    for (int ci = 0; ci < nc; ci++) {
        int c = s_list[ci];
        const float* crow = cb32 + (size_t)c * DD;
        float p = s_a[tid] * __ldg(&crow[tid]) + s_a[tid + 256] * __ldg(&crow[tid + 256]);
        #pragma unroll
        for (int off = 16; off > 0; off >>= 1) p += __shfl_down_sync(0xffffffffu, p, off);
        if ((tid & 31) == 0) s_fred[tid >> 5] = p;
        __syncthreads();
        if (tid == 0) {
            float dot = 0.0f;
            #pragma unroll
            for (int i = 0; i < 8; i++) dot += s_fred[i];
            float dd = norms[c] - 2.0f * dot;
            if (dd < bestd || (dd == bestd && c < bestc)) { bestd = dd; bestc = c; }
        }
        __syncthreads();
    }
    if (tid == 0) {
        s_bestc = bestc;
        g_indices[row * QQ + q] = bestc;
        atomicAdd(&g_hist2[q * CC + bestc], 1);
    }
    __syncthreads();

    // residual update + loss + forward row norm
    int c = s_bestc;
    const float* crow = cb32 + (size_t)c * DD;
    float lsum = 0.0f;
    #pragma unroll
    for (int k = tid; k < DD; k += 256) {
        float r = s_a[k] - crow[k];
        size_t gi = (size_t)row * DD + k;
        __half h = __float2half(r);
        g_res_h[gi] = h;
        g_res_l[gi] = __float2half(r - __half2float(h));
        lsum += r * r;
    }
    #pragma unroll
    for (int off = 16; off > 0; off >>= 1) lsum += __shfl_down_sync(0xffffffffu, lsum, off);
    if ((tid & 31) == 0) s_fred[tid >> 5] = lsum;
    __syncthreads();
    if (tid == 0) {
        float tot = 0.0f;
        #pragma unroll
        for (int i = 0; i < 8; i++) tot += s_fred[i];
        g_rnorm2[row] = tot;          // margin input for next stage
        atomicAdd(&g_loss[q], tot);
    }
}

// ---------------------------------------------------------------------------
// output: quantized_out (N,D,T) = x - residual_final  (transpose back)
// ---------------------------------------------------------------------------
__global__ void transpose_out_kernel(const float* __restrict__ x, float* __restrict__ out) {
    __shared__ float tile[32][33];
    int n  = blockIdx.z;
    int t0 = blockIdx.x * 32;
    int d0 = blockIdx.y * 32;
    int tx = threadIdx.x, ty = threadIdx.y;  // (32, 8)

    #pragma unroll
    for (int i = 0; i < 4; i++) {
        int t = t0 + ty + i * 8;
        size_t gi = (size_t)(n * TT + t) * DD + (d0 + tx);
        tile[ty + i * 8][tx] = __half2float(g_res_h[gi]) + __half2float(g_res_l[gi]);
    }
    __syncthreads();
    #pragma unroll
    for (int i = 0; i < 4; i++) {
        int d = d0 + ty + i * 8;
        size_t gi = (size_t)n * DD * TT + (size_t)d * TT + (t0 + tx);
        out[gi] = x[gi] - tile[tx][ty + i * 8];
    }
}

__global__ void idx_kernel(float* __restrict__ out) {
    int i = blockIdx.x * blockDim.x + threadIdx.x;
    if (i < OUT_IDX) out[OUT_QUANT + i] = (float)g_indices[i];
}

// all 6 perplexities + mean loss
__global__ void finalize_kernel(float* __restrict__ out) {
    int tid = threadIdx.x;   // 256
    __shared__ float ws[8];
    __shared__ float perp_sum;
    if (tid == 0) perp_sum = 0.0f;
    __syncthreads();

    for (int q = 0; q < QQ; q++) {
        float s = 0.0f;
        for (int i = tid; i < CC; i += 256) {
            float p = (float)g_hist2[q * CC + i] * (1.0f / (float)NT);
            s += p * logf(p + 1e-10f);
        }
        #pragma unroll
        for (int off = 16; off > 0; off >>= 1) s += __shfl_down_sync(0xffffffffu, s, off);
        if ((tid & 31) == 0) ws[tid >> 5] = s;
        __syncthreads();
        if (tid == 0) {
            float t = 0.0f;
            #pragma unroll
            for (int i = 0; i < 8; i++) t += ws[i];
            perp_sum += expf(-t);
        }
        __syncthreads();
    }

    if (tid == 0) {
        float l = 0.0f;
        #pragma unroll
        for (int q = 0; q < QQ; q++) l += g_loss[q];
        out[OUT_QUANT + OUT_IDX + 0] = l / ((float)NT * (float)DD) / (float)QQ;
        out[OUT_QUANT + OUT_IDX + 1] = perp_sum / (float)QQ;
    }
}

// ---------------------------------------------------------------------------
extern "C" void kernel_launch(void* const* d_in, const int* in_sizes, int n_in,
                              void* d_out, int out_size) {
    const float* x  = (const float*)d_in[0];   // (64, 512, 256) fp32
    const float* cb = (const float*)d_in[1];   // (6, 1024, 512) fp32
    float* out = (float*)d_out;

    static bool attr_set = false;
    if (!attr_set) {
        cudaFuncSetAttribute(dist_kernel,
                             cudaFuncAttributeMaxDynamicSharedMemorySize, ARG_SMEM);
        attr_set = true;
    }

    init_kernel<<<64, 256>>>();

    dim3 tb(32, 8);
    dim3 tg(TT / 32, DD / 32, NN);   // (8, 16, 64)
    transpose_in_kernel<<<tg, tb>>>(x);

    cbprep_kernel<<<QQ * CC, 128>>>(cb);

    for (int q = 0; q < QQ; q++) {
        const float* cbq = cb + (size_t)q * CC * DD;
        dist_kernel<<<GRID_ARG, 128, ARG_SMEM>>>(q);
        refine_update_kernel<<<NT, 256>>>(cbq, q);
    }

    transpose_out_kernel<<<tg, tb>>>(x, out);
    idx_kernel<<<(OUT_IDX + 255) / 256, 256>>>(out);
    finalize_kernel<<<1, 256>>>(out);
}

// round 13
// speedup vs baseline: 1.4495x; 1.1449x over previous
#include <cuda_runtime.h>
#include <cuda_fp16.h>
#include <cstdint>

// Problem constants
#define NN   64
#define DD   512
#define TT   256
#define QQ   6
#define CC   1024
#define NT   (NN*TT)              // 16384
#define OUT_QUANT   (NN*DD*TT)    // 8388608
#define OUT_IDX     (NT*QQ)       // 98304

// Scratch (device globals — no runtime allocation allowed)
__device__ __half g_res_h[(size_t)NT * DD];     // residual hi (fp16)
__device__ __half g_res_l[(size_t)NT * DD];     // residual lo (fp16)
__device__ __half g_cb_h[(size_t)QQ * CC * DD]; // codebook hi
__device__ float  g_cbnorm[QQ * CC];            // ||c||^2 per code per stage
__device__ __half g_dist[(size_t)NT * CC];      // hh-approx distances (fp16, 33MB)
__device__ float  g_rnorm2[NT];                 // ||residual_row||^2
__device__ int    g_cmax2[QQ];                  // max ||c||^2 per stage (float bits)
__device__ int    g_indices[NT * QQ];
__device__ int    g_hist2[QQ * CC];             // per-stage histograms
__device__ float  g_loss[QQ];

// ===========================================================================
// helpers
// ===========================================================================
__device__ __forceinline__ uint32_t smem_u32(const void* p) {
    uint32_t a;
    asm("{ .reg .u64 t; cvta.to.shared.u64 t, %1; cvt.u32.u64 %0, t; }" : "=r"(a) : "l"(p));
    return a;
}
__device__ __forceinline__ uint32_t swz(uint32_t off) {           // Swizzle<3,4,3>
    return off ^ ((off >> 3) & 0x70);
}
__device__ __forceinline__ unsigned int sortable_f32(float f) {
    unsigned int u = __float_as_uint(f);
    return (u & 0x80000000u) ? ~u : (u | 0x80000000u);
}

#define CP16(dst, src) \
    asm volatile("cp.async.ca.shared.global [%0], [%1], 16;" :: "r"(dst), "l"(src))
#define CP_COMMIT() asm volatile("cp.async.commit_group;" ::: "memory")
#define CP_WAIT0()  asm volatile("cp.async.wait_group 0;" ::: "memory")

__device__ __forceinline__ void ldsm_x4(uint32_t* r, uint32_t addr) {
    asm volatile("ldmatrix.sync.aligned.m8n8.x4.shared.b16 {%0,%1,%2,%3}, [%4];"
        : "=r"(r[0]), "=r"(r[1]), "=r"(r[2]), "=r"(r[3]) : "r"(addr));
}
__device__ __forceinline__ void mma_16816(float* d, const uint32_t* a,
                                          uint32_t b0, uint32_t b1) {
    asm volatile(
        "mma.sync.aligned.m16n8k16.row.col.f32.f16.f16.f32 "
        "{%0,%1,%2,%3}, {%4,%5,%6,%7}, {%8,%9}, {%0,%1,%2,%3};"
        : "+f"(d[0]), "+f"(d[1]), "+f"(d[2]), "+f"(d[3])
        : "r"(a[0]), "r"(a[1]), "r"(a[2]), "r"(a[3]), "r"(b0), "r"(b1));
}

// ===========================================================================
// init: zero hist2 + loss + rnorm2 + cmax (graph replays)
// ===========================================================================
__global__ void init_kernel() {
    int i = blockIdx.x * blockDim.x + threadIdx.x;   // grid 64 x 256 = 16384
    if (i < NT) g_rnorm2[i] = 0.0f;
    if (i < QQ * CC) g_hist2[i] = 0;
    if (i < QQ) { g_loss[i] = 0.0f; g_cmax2[i] = 0; }
}

// codebook prep: hi split, ||c||^2, per-stage max norm
__global__ void cbprep_kernel(const float* __restrict__ cb) {
    int code = blockIdx.x;             // 0..6143 (q*1024+c)
    int tid  = threadIdx.x;            // 128
    size_t base = (size_t)code * DD;
    float4 v = ((const float4*)(cb + base))[tid];

    __half2* hp = (__half2*)(g_cb_h + base + tid * 4);
    hp[0] = __halves2half2(__float2half(v.x), __float2half(v.y));
    hp[1] = __halves2half2(__float2half(v.z), __float2half(v.w));

    float s = v.x * v.x + v.y * v.y + v.z * v.z + v.w * v.w;
    #pragma unroll
    for (int off = 16; off > 0; off >>= 1) s += __shfl_down_sync(0xffffffffu, s, off);
    __shared__ float ws[4];
    if ((tid & 31) == 0) ws[tid >> 5] = s;
    __syncthreads();
    if (tid == 0) {
        float n = ws[0] + ws[1] + ws[2] + ws[3];
        g_cbnorm[code] = n;
        atomicMax(&g_cmax2[code >> 10], __float_as_int(n));  // norms > 0
    }
}

// transpose in: x (N, D, T) -> residual (NT, D) fp16 hi/lo; accumulate row norms
__global__ void transpose_in_kernel(const float* __restrict__ x) {
    __shared__ float tile[32][33];
    int n  = blockIdx.z;
    int t0 = blockIdx.x * 32;
    int d0 = blockIdx.y * 32;
    int tx = threadIdx.x, ty = threadIdx.y;  // (32, 8)

    #pragma unroll
    for (int i = 0; i < 4; i++) {
        int d = d0 + ty + i * 8;
        tile[ty + i * 8][tx] = x[(size_t)n * DD * TT + (size_t)d * TT + (t0 + tx)];
    }
    __syncthreads();
    #pragma unroll
    for (int i = 0; i < 4; i++) {
        int t = t0 + ty + i * 8;
        float v = tile[tx][ty + i * 8];
        size_t gi = (size_t)(n * TT + t) * DD + (d0 + tx);
        __half h = __float2half(v);
        g_res_h[gi] = h;
        g_res_l[gi] = __float2half(v - __half2float(h));
        float s = v * v;
        #pragma unroll
        for (int off = 16; off > 0; off >>= 1) s += __shfl_down_sync(0xffffffffu, s, off);
        if (tx == 0) atomicAdd(&g_rnorm2[n * TT + t], s);
    }
}

// ===========================================================================
// PASS 1: hh-only distance matrix, fp16 output, coalesced via smem staging.
// Persistent grid, tile = 64 rows x 128 codes x K512, 128 threads = 4 warps
// (2m x 2n), 8 MMAs per k16.
// ===========================================================================
#define MROWS   64
#define NCODES  128
#define KC      64
#define NCHUNK  (DD / KC)           // 8
#define NTILES  ((NT / MROWS) * (CC / NCODES))   // 2048
#define GRID_ARG 456

#define OFF_AH   0
#define OFF_BH   (8*1024)
#define BUF_BYTES (24*1024)
#define DSTRIDE  272                 // 64 rows x 272B staging (fits in 24KB buffer)
#define ARG_SMEM (2*BUF_BYTES)       // 49152

__global__ void __launch_bounds__(128) dist_kernel(int q) {
    extern __shared__ char smem[];
    const uint32_t sb = smem_u32(smem);
    const int tid  = threadIdx.x;
    const int lane = tid & 31;
    const int wid  = tid >> 5;
    const int wm   = wid & 1;          // 0..1  (32 rows each)
    const int wn   = wid >> 1;         // 0..1  (64 codes each)
    const int bid  = blockIdx.x;

    const __half* __restrict__ resh = g_res_h;
    const __half* __restrict__ cbh  = g_cb_h + (size_t)q * CC * DD;
    const float*  __restrict__ norms = g_cbnorm + q * CC;

    int ntiles = 0;
    for (int t = bid; t < NTILES; t += GRID_ARG) ntiles++;
    if (ntiles == 0) return;
    const int NG = ntiles * NCHUNK;

    float d[2][8][4];

    const int aRow  = (lane & 7) + ((lane >> 3) & 1) * 8;
    const int aK    = ((lane >> 4) & 1) * 8;
    const int bCode = (lane & 7) + ((lane >> 4) & 1) * 8;
    const int bK    = ((lane >> 3) & 1) * 8;

    auto issue = [&](int g) {
        const int t  = bid + GRID_ARG * (g >> 3);
        const int rb = (t & 255) * MROWS;
        const int ct = (t >> 8) * NCODES;
        const int k0 = (g & 7) * KC;
        const uint32_t bufb = sb + (g & 1) * BUF_BYTES;
        #pragma unroll
        for (int p = 0; p < 4; p++) {
            int seg = tid + p * 128;         // 0..511 (A: 64 rows x 8 segs)
            int row = seg >> 3, s8 = seg & 7;
            uint32_t so = swz((uint32_t)(row * 128 + s8 * 16));
            CP16(bufb + OFF_AH + so, resh + (size_t)(rb + row) * DD + k0 + s8 * 8);
        }
        #pragma unroll
        for (int p = 0; p < 8; p++) {
            int seg = tid + p * 128;         // 0..1023 (B: 128 codes x 8 segs)
            int row = seg >> 3, s8 = seg & 7;
            uint32_t so = swz((uint32_t)(row * 128 + s8 * 16));
            CP16(bufb + OFF_BH + so, cbh + (size_t)(ct + row) * DD + k0 + s8 * 8);
        }
        CP_COMMIT();
    };

    issue(0);
    for (int g = 0; g < NG; g++) {
        CP_WAIT0();
        __syncthreads();       // publish loads; also orders prior epilogue copy-reads

        if ((g & 7) == 0) {
            #pragma unroll
            for (int i = 0; i < 2; i++)
                #pragma unroll
                for (int j = 0; j < 8; j++)
                    #pragma unroll
                    for (int e = 0; e < 4; e++) d[i][j][e] = 0.0f;
        }

        if (g + 1 < NG) issue(g + 1);

        const uint32_t bufb = sb + (g & 1) * BUF_BYTES;
        #pragma unroll
        for (int kk = 0; kk < KC; kk += 16) {
            uint32_t ah[2][4];
            #pragma unroll
            for (int i = 0; i < 2; i++) {
                uint32_t so = swz((uint32_t)((wm * 32 + i * 16 + aRow) * 128 + (kk + aK) * 2));
                ldsm_x4(ah[i], bufb + OFF_AH + so);
            }
            #pragma unroll
            for (int j2 = 0; j2 < 4; j2++) {
                uint32_t bh[4];
                uint32_t so = swz((uint32_t)((wn * 64 + j2 * 16 + bCode) * 128 + (kk + bK) * 2));
                ldsm_x4(bh, bufb + OFF_BH + so);
                #pragma unroll
                for (int i = 0; i < 2; i++)
                    #pragma unroll
                    for (int h = 0; h < 2; h++)
                        mma_16816(d[i][j2 * 2 + h], ah[i], bh[h * 2], bh[h * 2 + 1]);
            }
        }

        // ---- tile epilogue: distances -> smem staging -> coalesced fp16 ----
        if ((g & 7) == 7) {
            const int t  = bid + GRID_ARG * (g >> 3);
            const int rb = (t & 255) * MROWS;
            const int ct = (t >> 8) * NCODES;
            char* stg = smem + (g & 1) * BUF_BYTES;   // dead until issue(g+2)

            // CRITICAL: all warps must finish their ldsm reads of this buffer
            // before any warp overwrites it with staging data (cross-warp WAR).
            __syncthreads();

            #pragma unroll
            for (int i = 0; i < 2; i++)
                #pragma unroll
                for (int j = 0; j < 8; j++)
                    #pragma unroll
                    for (int e2 = 0; e2 < 2; e2++) {
                        int rowL = wm * 32 + i * 16 + (lane >> 2) + e2 * 8;
                        int colL = wn * 64 + j * 8 + 2 * (lane & 3);
                        float dx = __ldg(&norms[ct + colL])     - 2.0f * d[i][j][e2 * 2 + 0];
                        float dy = __ldg(&norms[ct + colL + 1]) - 2.0f * d[i][j][e2 * 2 + 1];
                        *(__half2*)(stg + rowL * DSTRIDE + colL * 2) =
                            __halves2half2(__float2half(dx), __float2half(dy));
                    }
            __syncthreads();
            // coalesced copy: 64 rows x 256B (16B per thread-seg)
            #pragma unroll
            for (int p = 0; p < 8; p++) {
                int seg = tid + p * 128;     // 0..1023
                int rowL = seg >> 4, c16 = seg & 15;
                uint4 v = *(uint4*)(stg + rowL * DSTRIDE + c16 * 16);
                *(uint4*)((char*)(g_dist + (size_t)(rb + rowL) * CC + ct) + c16 * 16) = v;
            }
            // next iteration's CP_WAIT0 + __syncthreads orders these reads
            // before issue(g+2) refills this buffer.
        }
    }
}

// ===========================================================================
// PASS 2: per-row candidate refine + residual update + loss + histogram.
// One block per row, 256 threads.
// ===========================================================================
__global__ void __launch_bounds__(256) refine_update_kernel(const float* __restrict__ cb32, int q) {
    const int row = blockIdx.x;
    const int tid = threadIdx.x;
    __shared__ float s_a[DD];                 // exact residual (h+l), 2KB
    __shared__ unsigned long long s_red[8];
    __shared__ float s_fred[8];
    __shared__ int s_list[128];
    __shared__ int s_cnt;
    __shared__ int s_bestc;
    __shared__ float s_dmin;

    const float* __restrict__ norms = g_cbnorm + q * CC;

    // reconstruct exact residual row
    #pragma unroll
    for (int k = tid; k < DD; k += 256) {
        size_t gi = (size_t)row * DD + k;
        s_a[k] = __half2float(g_res_h[gi]) + __half2float(g_res_l[gi]);
    }
    if (tid == 0) s_cnt = 0;

    // load d_hh (4 fp16 per thread) + local argmin (ascending index)
    const __half2* drow = (const __half2*)(g_dist + (size_t)row * CC);
    __half2 h01 = drow[tid * 2], h23 = drow[tid * 2 + 1];
    float d0 = __low2float(h01), d1 = __high2float(h01);
    float d2 = __low2float(h23), d3 = __high2float(h23);
    float bv = d0; int bi = tid * 4;
    if (d1 < bv) { bv = d1; bi = tid * 4 + 1; }
    if (d2 < bv) { bv = d2; bi = tid * 4 + 2; }
    if (d3 < bv) { bv = d3; bi = tid * 4 + 3; }
    unsigned long long key = ((unsigned long long)sortable_f32(bv) << 32) | (unsigned)bi;
    #pragma unroll
    for (int off = 16; off > 0; off >>= 1) {
        unsigned long long o = __shfl_down_sync(0xffffffffu, key, off);
        if (o < key) key = o;
    }
    if ((tid & 31) == 0) s_red[tid >> 5] = key;
    __syncthreads();
    if (tid == 0) {
        unsigned long long k0 = s_red[0];
        #pragma unroll
        for (int i = 1; i < 8; i++) if (s_red[i] < k0) k0 = s_red[i];
        unsigned u = (unsigned)(k0 >> 32);
        s_dmin = __uint_as_float((u & 0x80000000u) ? (u & 0x7FFFFFFFu) : ~u);
    }
    __syncthreads();

    // margin: |d_exact - d_hh| <= 2^-8 * ||a|| * ||c|| (pairwise, x2 safety)
    // +1.0 absorbs fp16 storage quantization of d values (~0.5 ulp at d~512, both sides)
    float cmax = sqrtf(__int_as_float(g_cmax2[q]));
    float eps  = sqrtf(g_rnorm2[row]) * cmax * (1.0f / 128.0f) + 1.0f;
    float T = s_dmin + eps;

    int base = tid * 4;
    if (d0 <= T) { int p = atomicAdd(&s_cnt, 1); if (p < 128) s_list[p] = base; }
    if (d1 <= T) { int p = atomicAdd(&s_cnt, 1); if (p < 128) s_list[p] = base + 1; }
    if (d2 <= T) { int p = atomicAdd(&s_cnt, 1); if (p < 128) s_list[p] = base + 2; }
    if (d3 <= T) { int p = atomicAdd(&s_cnt, 1); if (p < 128) s_list[p] = base + 3; }
    __syncthreads();
    int nc = min(s_cnt, 128);

    // exact fp32 refinement over candidates
    float bestd = 3.4e38f;
    int   bestc = CC;
    for (int ci = 0; ci < nc; ci++) {
        int c = s_list[ci];
        const float* crow = cb32 + (size_t)c * DD;
        float p = s_a[tid] * __ldg(&crow[tid]) + s_a[tid + 256] * __ldg(&crow[tid + 256]);
        #pragma unroll
        for (int off = 16; off > 0; off >>= 1) p += __shfl_down_sync(0xffffffffu, p, off);
        if ((tid & 31) == 0) s_fred[tid >> 5] = p;
        __syncthreads();
        if (tid == 0) {
            float dot = 0.0f;
            #pragma unroll
            for (int i = 0; i < 8; i++) dot += s_fred[i];
            float dd = norms[c] - 2.0f * dot;
            if (dd < bestd || (dd == bestd && c < bestc)) { bestd = dd; bestc = c; }
        }
        __syncthreads();
    }
    if (tid == 0) {
        s_bestc = bestc;
        g_indices[row * QQ + q] = bestc;
        atomicAdd(&g_hist2[q * CC + bestc], 1);
    }
    __syncthreads();

    // residual update + loss + forward row norm
    int c = s_bestc;
    const float* crow = cb32 + (size_t)c * DD;
    float lsum = 0.0f;
    #pragma unroll
    for (int k = tid; k < DD; k += 256) {
        float r = s_a[k] - crow[k];
        size_t gi = (size_t)row * DD + k;
        __half h = __float2half(r);
        g_res_h[gi] = h;
        g_res_l[gi] = __float2half(r - __half2float(h));
        lsum += r * r;
    }
    #pragma unroll
    for (int off = 16; off > 0; off >>= 1) lsum += __shfl_down_sync(0xffffffffu, lsum, off);
    if ((tid & 31) == 0) s_fred[tid >> 5] = lsum;
    __syncthreads();
    if (tid == 0) {
        float tot = 0.0f;
        #pragma unroll
        for (int i = 0; i < 8; i++) tot += s_fred[i];
        g_rnorm2[row] = tot;          // margin input for next stage
        atomicAdd(&g_loss[q], tot);
    }
}

// ---------------------------------------------------------------------------
// output: quantized_out (N,D,T) = x - residual_final  (transpose back)
// ---------------------------------------------------------------------------
__global__ void transpose_out_kernel(const float* __restrict__ x, float* __restrict__ out) {
    __shared__ float tile[32][33];
    int n  = blockIdx.z;
    int t0 = blockIdx.x * 32;
    int d0 = blockIdx.y * 32;
    int tx = threadIdx.x, ty = threadIdx.y;  // (32, 8)

    #pragma unroll
    for (int i = 0; i < 4; i++) {
        int t = t0 + ty + i * 8;
        size_t gi = (size_t)(n * TT + t) * DD + (d0 + tx);
        tile[ty + i * 8][tx] = __half2float(g_res_h[gi]) + __half2float(g_res_l[gi]);
    }
    __syncthreads();
    #pragma unroll
    for (int i = 0; i < 4; i++) {
        int d = d0 + ty + i * 8;
        size_t gi = (size_t)n * DD * TT + (size_t)d * TT + (t0 + tx);
        out[gi] = x[gi] - tile[tx][ty + i * 8];
    }
}

__global__ void idx_kernel(float* __restrict__ out) {
    int i = blockIdx.x * blockDim.x + threadIdx.x;
    if (i < OUT_IDX) out[OUT_QUANT + i] = (float)g_indices[i];
}

// all 6 perplexities + mean loss
__global__ void finalize_kernel(float* __restrict__ out) {
    int tid = threadIdx.x;   // 256
    __shared__ float ws[8];
    __shared__ float perp_sum;
    if (tid == 0) perp_sum = 0.0f;
    __syncthreads();

    for (int q = 0; q < QQ; q++) {
        float s = 0.0f;
        for (int i = tid; i < CC; i += 256) {
            float p = (float)g_hist2[q * CC + i] * (1.0f / (float)NT);
            s += p * logf(p + 1e-10f);
        }
        #pragma unroll
        for (int off = 16; off > 0; off >>= 1) s += __shfl_down_sync(0xffffffffu, s, off);
        if ((tid & 31) == 0) ws[tid >> 5] = s;
        __syncthreads();
        if (tid == 0) {
            float t = 0.0f;
            #pragma unroll
            for (int i = 0; i < 8; i++) t += ws[i];
            perp_sum += expf(-t);
        }
        __syncthreads();
    }

    if (tid == 0) {
        float l = 0.0f;
        #pragma unroll
        for (int q = 0; q < QQ; q++) l += g_loss[q];
        out[OUT_QUANT + OUT_IDX + 0] = l / ((float)NT * (float)DD) / (float)QQ;
        out[OUT_QUANT + OUT_IDX + 1] = perp_sum / (float)QQ;
    }
}

// ---------------------------------------------------------------------------
extern "C" void kernel_launch(void* const* d_in, const int* in_sizes, int n_in,
                              void* d_out, int out_size) {
    const float* x  = (const float*)d_in[0];   // (64, 512, 256) fp32
    const float* cb = (const float*)d_in[1];   // (6, 1024, 512) fp32
    float* out = (float*)d_out;

    static bool attr_set = false;
    if (!attr_set) {
        cudaFuncSetAttribute(dist_kernel,
                             cudaFuncAttributeMaxDynamicSharedMemorySize, ARG_SMEM);
        attr_set = true;
    }

    init_kernel<<<64, 256>>>();

    dim3 tb(32, 8);
    dim3 tg(TT / 32, DD / 32, NN);   // (8, 16, 64)
    transpose_in_kernel<<<tg, tb>>>(x);

    cbprep_kernel<<<QQ * CC, 128>>>(cb);

    for (int q = 0; q < QQ; q++) {
        const float* cbq = cb + (size_t)q * CC * DD;
        dist_kernel<<<GRID_ARG, 128, ARG_SMEM>>>(q);
        refine_update_kernel<<<NT, 256>>>(cbq, q);
    }

    transpose_out_kernel<<<tg, tb>>>(x, out);
    idx_kernel<<<(OUT_IDX + 255) / 256, 256>>>(out);
    finalize_kernel<<<1, 256>>>(out);
}

// round 14
// speedup vs baseline: 1.6266x; 1.1222x over previous
#include <cuda_runtime.h>
#include <cuda_fp16.h>
#include <cstdint>

// Problem constants
#define NN   64
#define DD   512
#define TT   256
#define QQ   6
#define CC   1024
#define NT   (NN*TT)              // 16384
#define OUT_QUANT   (NN*DD*TT)    // 8388608
#define OUT_IDX     (NT*QQ)       // 98304

// Scratch (device globals — no runtime allocation allowed)
__device__ __half g_res_h[(size_t)NT * DD];     // residual hi (fp16)
__device__ __half g_res_l[(size_t)NT * DD];     // residual lo (fp16)
__device__ __half g_cb_h[(size_t)QQ * CC * DD]; // codebook hi
__device__ float  g_cbnorm[QQ * CC];            // ||c||^2 per code per stage
__device__ __half g_dist[(size_t)NT * CC];      // hh-approx distances (fp16, 33MB)
__device__ float  g_rnorm2[NT];                 // ||residual_row||^2
__device__ int    g_cmax2[QQ];                  // max ||c||^2 per stage (float bits)
__device__ int    g_indices[NT * QQ];
__device__ int    g_hist2[QQ * CC];             // per-stage histograms
__device__ float  g_loss[QQ];

// ===========================================================================
// helpers
// ===========================================================================
__device__ __forceinline__ uint32_t smem_u32(const void* p) {
    uint32_t a;
    asm("{ .reg .u64 t; cvta.to.shared.u64 t, %1; cvt.u32.u64 %0, t; }" : "=r"(a) : "l"(p));
    return a;
}
__device__ __forceinline__ uint32_t swz(uint32_t off) {           // Swizzle<3,4,3>
    return off ^ ((off >> 3) & 0x70);
}
__device__ __forceinline__ unsigned int sortable_f32(float f) {
    unsigned int u = __float_as_uint(f);
    return (u & 0x80000000u) ? ~u : (u | 0x80000000u);
}

#define CP16(dst, src) \
    asm volatile("cp.async.ca.shared.global [%0], [%1], 16;" :: "r"(dst), "l"(src))
#define CP_COMMIT() asm volatile("cp.async.commit_group;" ::: "memory")
#define CP_WAIT0()  asm volatile("cp.async.wait_group 0;" ::: "memory")

__device__ __forceinline__ void ldsm_x4(uint32_t* r, uint32_t addr) {
    asm volatile("ldmatrix.sync.aligned.m8n8.x4.shared.b16 {%0,%1,%2,%3}, [%4];"
        : "=r"(r[0]), "=r"(r[1]), "=r"(r[2]), "=r"(r[3]) : "r"(addr));
}
__device__ __forceinline__ void mma_16816(float* d, const uint32_t* a,
                                          uint32_t b0, uint32_t b1) {
    asm volatile(
        "mma.sync.aligned.m16n8k16.row.col.f32.f16.f16.f32 "
        "{%0,%1,%2,%3}, {%4,%5,%6,%7}, {%8,%9}, {%0,%1,%2,%3};"
        : "+f"(d[0]), "+f"(d[1]), "+f"(d[2]), "+f"(d[3])
        : "r"(a[0]), "r"(a[1]), "r"(a[2]), "r"(a[3]), "r"(b0), "r"(b1));
}

// ===========================================================================
// init: zero hist2 + loss + rnorm2 + cmax (graph replays)
// ===========================================================================
__global__ void init_kernel() {
    int i = blockIdx.x * blockDim.x + threadIdx.x;   // grid 64 x 256 = 16384
    if (i < NT) g_rnorm2[i] = 0.0f;
    if (i < QQ * CC) g_hist2[i] = 0;
    if (i < QQ) { g_loss[i] = 0.0f; g_cmax2[i] = 0; }
}

// codebook prep: hi split, ||c||^2, per-stage max norm
__global__ void cbprep_kernel(const float* __restrict__ cb) {
    int code = blockIdx.x;             // 0..6143 (q*1024+c)
    int tid  = threadIdx.x;            // 128
    size_t base = (size_t)code * DD;
    float4 v = ((const float4*)(cb + base))[tid];

    __half2* hp = (__half2*)(g_cb_h + base + tid * 4);
    hp[0] = __halves2half2(__float2half(v.x), __float2half(v.y));
    hp[1] = __halves2half2(__float2half(v.z), __float2half(v.w));

    float s = v.x * v.x + v.y * v.y + v.z * v.z + v.w * v.w;
    #pragma unroll
    for (int off = 16; off > 0; off >>= 1) s += __shfl_down_sync(0xffffffffu, s, off);
    __shared__ float ws[4];
    if ((tid & 31) == 0) ws[tid >> 5] = s;
    __syncthreads();
    if (tid == 0) {
        float n = ws[0] + ws[1] + ws[2] + ws[3];
        g_cbnorm[code] = n;
        atomicMax(&g_cmax2[code >> 10], __float_as_int(n));  // norms > 0
    }
}

// transpose in: x (N, D, T) -> residual (NT, D) fp16 hi/lo; accumulate row norms
__global__ void transpose_in_kernel(const float* __restrict__ x) {
    __shared__ float tile[32][33];
    int n  = blockIdx.z;
    int t0 = blockIdx.x * 32;
    int d0 = blockIdx.y * 32;
    int tx = threadIdx.x, ty = threadIdx.y;  // (32, 8)

    #pragma unroll
    for (int i = 0; i < 4; i++) {
        int d = d0 + ty + i * 8;
        tile[ty + i * 8][tx] = x[(size_t)n * DD * TT + (size_t)d * TT + (t0 + tx)];
    }
    __syncthreads();
    #pragma unroll
    for (int i = 0; i < 4; i++) {
        int t = t0 + ty + i * 8;
        float v = tile[tx][ty + i * 8];
        size_t gi = (size_t)(n * TT + t) * DD + (d0 + tx);
        __half h = __float2half(v);
        g_res_h[gi] = h;
        g_res_l[gi] = __float2half(v - __half2float(h));
        float s = v * v;
        #pragma unroll
        for (int off = 16; off > 0; off >>= 1) s += __shfl_down_sync(0xffffffffu, s, off);
        if (tx == 0) atomicAdd(&g_rnorm2[n * TT + t], s);
    }
}

// ===========================================================================
// PASS 1: hh-only distance matrix, fp16 output, coalesced via DEDICATED
// smem staging (no WAR with compute buffers). Persistent grid, tile =
// 64 rows x 128 codes x K512, 128 threads = 4 warps (2m x 2n).
// ===========================================================================
#define MROWS   64
#define NCODES  128
#define KC      64
#define NCHUNK  (DD / KC)           // 8
#define NTILES  ((NT / MROWS) * (CC / NCODES))   // 2048
#define GRID_ARG 456

#define OFF_AH   0
#define OFF_BH   (8*1024)
#define BUF_BYTES (24*1024)
#define DSTRIDE  272
#define OFF_STG  (2*BUF_BYTES)                   // dedicated staging
#define ARG_SMEM (2*BUF_BYTES + MROWS*DSTRIDE)   // 49152 + 17408 = 66560

__global__ void __launch_bounds__(128) dist_kernel(int q) {
    extern __shared__ char smem[];
    const uint32_t sb = smem_u32(smem);
    const int tid  = threadIdx.x;
    const int lane = tid & 31;
    const int wid  = tid >> 5;
    const int wm   = wid & 1;          // 0..1  (32 rows each)
    const int wn   = wid >> 1;         // 0..1  (64 codes each)
    const int bid  = blockIdx.x;

    const __half* __restrict__ resh = g_res_h;
    const __half* __restrict__ cbh  = g_cb_h + (size_t)q * CC * DD;
    const float*  __restrict__ norms = g_cbnorm + q * CC;

    int ntiles = 0;
    for (int t = bid; t < NTILES; t += GRID_ARG) ntiles++;
    if (ntiles == 0) return;
    const int NG = ntiles * NCHUNK;

    float d[2][8][4];

    const int aRow  = (lane & 7) + ((lane >> 3) & 1) * 8;
    const int aK    = ((lane >> 4) & 1) * 8;
    const int bCode = (lane & 7) + ((lane >> 4) & 1) * 8;
    const int bK    = ((lane >> 3) & 1) * 8;

    auto issue = [&](int g) {
        const int t  = bid + GRID_ARG * (g >> 3);
        const int rb = (t & 255) * MROWS;
        const int ct = (t >> 8) * NCODES;
        const int k0 = (g & 7) * KC;
        const uint32_t bufb = sb + (g & 1) * BUF_BYTES;
        #pragma unroll
        for (int p = 0; p < 4; p++) {
            int seg = tid + p * 128;         // 0..511 (A: 64 rows x 8 segs)
            int row = seg >> 3, s8 = seg & 7;
            uint32_t so = swz((uint32_t)(row * 128 + s8 * 16));
            CP16(bufb + OFF_AH + so, resh + (size_t)(rb + row) * DD + k0 + s8 * 8);
        }
        #pragma unroll
        for (int p = 0; p < 8; p++) {
            int seg = tid + p * 128;         // 0..1023 (B: 128 codes x 8 segs)
            int row = seg >> 3, s8 = seg & 7;
            uint32_t so = swz((uint32_t)(row * 128 + s8 * 16));
            CP16(bufb + OFF_BH + so, cbh + (size_t)(ct + row) * DD + k0 + s8 * 8);
        }
        CP_COMMIT();
    };

    issue(0);
    for (int g = 0; g < NG; g++) {
        CP_WAIT0();
        __syncthreads();       // publish loads; also orders prior staging copy-reads

        if ((g & 7) == 0) {
            #pragma unroll
            for (int i = 0; i < 2; i++)
                #pragma unroll
                for (int j = 0; j < 8; j++)
                    #pragma unroll
                    for (int e = 0; e < 4; e++) d[i][j][e] = 0.0f;
        }

        if (g + 1 < NG) issue(g + 1);

        const uint32_t bufb = sb + (g & 1) * BUF_BYTES;
        #pragma unroll
        for (int kk = 0; kk < KC; kk += 16) {
            uint32_t ah[2][4];
            #pragma unroll
            for (int i = 0; i < 2; i++) {
                uint32_t so = swz((uint32_t)((wm * 32 + i * 16 + aRow) * 128 + (kk + aK) * 2));
                ldsm_x4(ah[i], bufb + OFF_AH + so);
            }
            #pragma unroll
            for (int j2 = 0; j2 < 4; j2++) {
                uint32_t bh[4];
                uint32_t so = swz((uint32_t)((wn * 64 + j2 * 16 + bCode) * 128 + (kk + bK) * 2));
                ldsm_x4(bh, bufb + OFF_BH + so);
                #pragma unroll
                for (int i = 0; i < 2; i++)
                    #pragma unroll
                    for (int h = 0; h < 2; h++)
                        mma_16816(d[i][j2 * 2 + h], ah[i], bh[h * 2], bh[h * 2 + 1]);
            }
        }

        // ---- tile epilogue: distances -> dedicated staging -> coalesced fp16
        if ((g & 7) == 7) {
            const int t  = bid + GRID_ARG * (g >> 3);
            const int rb = (t & 255) * MROWS;
            const int ct = (t >> 8) * NCODES;
            char* stg = smem + OFF_STG;   // disjoint from compute buffers
            #pragma unroll
            for (int i = 0; i < 2; i++)
                #pragma unroll
                for (int j = 0; j < 8; j++)
                    #pragma unroll
                    for (int e2 = 0; e2 < 2; e2++) {
                        int rowL = wm * 32 + i * 16 + (lane >> 2) + e2 * 8;
                        int colL = wn * 64 + j * 8 + 2 * (lane & 3);
                        float dx = __ldg(&norms[ct + colL])     - 2.0f * d[i][j][e2 * 2 + 0];
                        float dy = __ldg(&norms[ct + colL + 1]) - 2.0f * d[i][j][e2 * 2 + 1];
                        *(__half2*)(stg + rowL * DSTRIDE + colL * 2) =
                            __halves2half2(__float2half(dx), __float2half(dy));
                    }
            __syncthreads();   // staging writes visible to all warps
            // coalesced copy: 64 rows x 256B (16B per thread-seg)
            #pragma unroll
            for (int p = 0; p < 8; p++) {
                int seg = tid + p * 128;     // 0..1023
                int rowL = seg >> 4, c16 = seg & 15;
                uint4 v = *(uint4*)(stg + rowL * DSTRIDE + c16 * 16);
                *(uint4*)((char*)(g_dist + (size_t)(rb + rowL) * CC + ct) + c16 * 16) = v;
            }
            // next tile's epilogue is 8 chunks (8 barriers) away -> staging safe
        }
    }
}

// ===========================================================================
// PASS 2 (warp-synchronous): one warp per row, 2 rows per warp.
// grid = 1024 blocks x 256 threads. No block barriers in the hot path.
// ===========================================================================
#define RWARPS 8
#define ROWS_PER_WARP 2
#define RBLOCKS (NT / (RWARPS * ROWS_PER_WARP))   // 1024

__global__ void __launch_bounds__(256) refine_update_kernel(const float* __restrict__ cb32, int q) {
    const int tid  = threadIdx.x;
    const int lane = tid & 31;
    const int wid  = tid >> 5;
    __shared__ float s_loss;
    if (tid == 0) s_loss = 0.0f;
    __syncthreads();

    const float* __restrict__ norms = g_cbnorm + q * CC;
    const float cmax = sqrtf(__int_as_float(g_cmax2[q]));

    #pragma unroll
    for (int r = 0; r < ROWS_PER_WARP; r++) {
        const int row = blockIdx.x * (RWARPS * ROWS_PER_WARP) + wid * ROWS_PER_WARP + r;

        // ---- load exact residual: a[2*j+e] <-> k = j*64 + lane*2 + e ----
        float a[16];
        const __half2* hr = (const __half2*)(g_res_h + (size_t)row * DD);
        const __half2* lr = (const __half2*)(g_res_l + (size_t)row * DD);
        #pragma unroll
        for (int j = 0; j < 8; j++) {
            __half2 h = hr[j * 32 + lane], l = lr[j * 32 + lane];
            a[2 * j]     = __low2float(h)  + __low2float(l);
            a[2 * j + 1] = __high2float(h) + __high2float(l);
        }

        // ---- load d_hh (32 values per lane) + lane argmin (ascending c) ----
        const __half2* drow = (const __half2*)(g_dist + (size_t)row * CC);
        __half2 dh[16];
        float bv = 3.4e38f; int bi = 0;
        #pragma unroll
        for (int it = 0; it < 16; it++) {
            dh[it] = drow[it * 32 + lane];
            float dx = __low2float(dh[it]), dy = __high2float(dh[it]);
            int c0 = (it * 32 + lane) * 2;
            if (dx < bv) { bv = dx; bi = c0; }
            if (dy < bv) { bv = dy; bi = c0 + 1; }
        }
        unsigned long long key =
            ((unsigned long long)sortable_f32(bv) << 32) | (unsigned)bi;
        #pragma unroll
        for (int off = 16; off > 0; off >>= 1) {
            unsigned long long o = __shfl_xor_sync(0xffffffffu, key, off);
            if (o < key) key = o;
        }
        unsigned u = (unsigned)(key >> 32);
        float dmin = __uint_as_float((u & 0x80000000u) ? (u & 0x7FFFFFFFu) : ~u);

        // margin (same bound as round 13: pairwise fp16 dot + storage quant)
        float eps = sqrtf(g_rnorm2[row]) * cmax * (1.0f / 128.0f) + 1.0f;
        float T = dmin + eps;

        // ---- count candidates ----
        int ncand = 0;
        #pragma unroll
        for (int it = 0; it < 16; it++) {
            float dx = __low2float(dh[it]), dy = __high2float(dh[it]);
            ncand += __popc(__ballot_sync(0xffffffffu, dx <= T));
            ncand += __popc(__ballot_sync(0xffffffffu, dy <= T));
        }

        int bc;
        if (ncand == 1) {
            bc = (int)(unsigned)(key & 0xFFFFFFFFull);   // unique candidate = hh-argmin
        } else {
            // exact fp32 refinement over candidates (order-independent tie-break)
            float bd = 3.4e38f; bc = CC;
            #pragma unroll 4
            for (int it = 0; it < 16; it++) {
                float dx = __low2float(dh[it]), dy = __high2float(dh[it]);
                #pragma unroll
                for (int e = 0; e < 2; e++) {
                    unsigned mask = __ballot_sync(0xffffffffu, (e ? dy : dx) <= T);
                    while (mask) {
                        int src = __ffs(mask) - 1; mask &= mask - 1;
                        int c = (it * 32 + src) * 2 + e;
                        const float* crow = cb32 + (size_t)c * DD;
                        float p = 0.0f;
                        #pragma unroll
                        for (int j = 0; j < 8; j++) {
                            float2 cv = *(const float2*)(crow + j * 64 + lane * 2);
                            p += a[2 * j] * cv.x + a[2 * j + 1] * cv.y;
                        }
                        #pragma unroll
                        for (int off = 16; off > 0; off >>= 1)
                            p += __shfl_xor_sync(0xffffffffu, p, off);
                        float dd = norms[c] - 2.0f * p;
                        if (dd < bd || (dd == bd && c < bc)) { bd = dd; bc = c; }
                    }
                }
            }
        }

        if (lane == 0) {
            g_indices[row * QQ + q] = bc;
            atomicAdd(&g_hist2[q * CC + bc], 1);
        }

        // ---- residual update + loss + forward row norm ----
        const float* crow = cb32 + (size_t)bc * DD;
        __half2* hw = (__half2*)(g_res_h + (size_t)row * DD);
        __half2* lw = (__half2*)(g_res_l + (size_t)row * DD);
        float lsum = 0.0f;
        #pragma unroll
        for (int j = 0; j < 8; j++) {
            float2 cv = *(const float2*)(crow + j * 64 + lane * 2);
            float r0 = a[2 * j] - cv.x;
            float r1 = a[2 * j + 1] - cv.y;
            __half h0 = __float2half(r0), h1 = __float2half(r1);
            hw[j * 32 + lane] = __halves2half2(h0, h1);
            lw[j * 32 + lane] = __halves2half2(__float2half(r0 - __half2float(h0)),
                                               __float2half(r1 - __half2float(h1)));
            lsum += r0 * r0 + r1 * r1;
        }
        #pragma unroll
        for (int off = 16; off > 0; off >>= 1)
            lsum += __shfl_xor_sync(0xffffffffu, lsum, off);
        if (lane == 0) {
            g_rnorm2[row] = lsum;
            atomicAdd(&s_loss, lsum);
        }
    }

    __syncthreads();
    if (tid == 0) atomicAdd(&g_loss[q], s_loss);
}

// ---------------------------------------------------------------------------
// output: quantized_out (N,D,T) = x - residual_final  (transpose back)
// ---------------------------------------------------------------------------
__global__ void transpose_out_kernel(const float* __restrict__ x, float* __restrict__ out) {
    __shared__ float tile[32][33];
    int n  = blockIdx.z;
    int t0 = blockIdx.x * 32;
    int d0 = blockIdx.y * 32;
    int tx = threadIdx.x, ty = threadIdx.y;  // (32, 8)

    #pragma unroll
    for (int i = 0; i < 4; i++) {
        int t = t0 + ty + i * 8;
        size_t gi = (size_t)(n * TT + t) * DD + (d0 + tx);
        tile[ty + i * 8][tx] = __half2float(g_res_h[gi]) + __half2float(g_res_l[gi]);
    }
    __syncthreads();
    #pragma unroll
    for (int i = 0; i < 4; i++) {
        int d = d0 + ty + i * 8;
        size_t gi = (size_t)n * DD * TT + (size_t)d * TT + (t0 + tx);
        out[gi] = x[gi] - tile[tx][ty + i * 8];
    }
}

__global__ void idx_kernel(float* __restrict__ out) {
    int i = blockIdx.x * blockDim.x + threadIdx.x;
    if (i < OUT_IDX) out[OUT_QUANT + i] = (float)g_indices[i];
}

// all 6 perplexities + mean loss
__global__ void finalize_kernel(float* __restrict__ out) {
    int tid = threadIdx.x;   // 256
    __shared__ float ws[8];
    __shared__ float perp_sum;
    if (tid == 0) perp_sum = 0.0f;
    __syncthreads();

    for (int q = 0; q < QQ; q++) {
        float s = 0.0f;
        for (int i = tid; i < CC; i += 256) {
            float p = (float)g_hist2[q * CC + i] * (1.0f / (float)NT);
            s += p * logf(p + 1e-10f);
        }
        #pragma unroll
        for (int off = 16; off > 0; off >>= 1) s += __shfl_down_sync(0xffffffffu, s, off);
        if ((tid & 31) == 0) ws[tid >> 5] = s;
        __syncthreads();
        if (tid == 0) {
            float t = 0.0f;
            #pragma unroll
            for (int i = 0; i < 8; i++) t += ws[i];
            perp_sum += expf(-t);
        }
        __syncthreads();
    }

    if (tid == 0) {
        float l = 0.0f;
        #pragma unroll
        for (int q = 0; q < QQ; q++) l += g_loss[q];
        out[OUT_QUANT + OUT_IDX + 0] = l / ((float)NT * (float)DD) / (float)QQ;
        out[OUT_QUANT + OUT_IDX + 1] = perp_sum / (float)QQ;
    }
}

// ---------------------------------------------------------------------------
extern "C" void kernel_launch(void* const* d_in, const int* in_sizes, int n_in,
                              void* d_out, int out_size) {
    const float* x  = (const float*)d_in[0];   // (64, 512, 256) fp32
    const float* cb = (const float*)d_in[1];   // (6, 1024, 512) fp32
    float* out = (float*)d_out;

    static bool attr_set = false;
    if (!attr_set) {
        cudaFuncSetAttribute(dist_kernel,
                             cudaFuncAttributeMaxDynamicSharedMemorySize, ARG_SMEM);
        attr_set = true;
    }

    init_kernel<<<64, 256>>>();

    dim3 tb(32, 8);
    dim3 tg(TT / 32, DD / 32, NN);   // (8, 16, 64)
    transpose_in_kernel<<<tg, tb>>>(x);

    cbprep_kernel<<<QQ * CC, 128>>>(cb);

    for (int q = 0; q < QQ; q++) {
        const float* cbq = cb + (size_t)q * CC * DD;
        dist_kernel<<<GRID_ARG, 128, ARG_SMEM>>>(q);
        refine_update_kernel<<<RBLOCKS, 256>>>(cbq, q);
    }

    transpose_out_kernel<<<tg, tb>>>(x, out);
    idx_kernel<<<(OUT_IDX + 255) / 256, 256>>>(out);
    finalize_kernel<<<1, 256>>>(out);
}

// round 15
// speedup vs baseline: 1.6895x; 1.0387x over previous
#include <cuda_runtime.h>
#include <cuda_fp16.h>
#include <cstdint>

// Problem constants
#define NN   64
#define DD   512
#define TT   256
#define QQ   6
#define CC   1024
#define NT   (NN*TT)              // 16384
#define OUT_QUANT   (NN*DD*TT)    // 8388608
#define OUT_IDX     (NT*QQ)       // 98304

// Scratch (device globals — no runtime allocation allowed)
__device__ __half g_res_h[(size_t)NT * DD];     // residual hi (fp16)
__device__ __half g_res_l[(size_t)NT * DD];     // residual lo (fp16)
__device__ __half g_cb_h[(size_t)QQ * CC * DD]; // codebook hi
__device__ float  g_cbnorm[QQ * CC];            // ||c||^2 per code per stage
__device__ __half g_dist[(size_t)NT * CC];      // hh-approx distances (fp16, 33MB)
__device__ float  g_rnorm2[NT];                 // ||residual_row||^2
__device__ int    g_cmax2[QQ];                  // max ||c||^2 per stage (float bits)
__device__ int    g_indices[NT * QQ];
__device__ int    g_hist2[QQ * CC];             // per-stage histograms
__device__ float  g_loss[QQ];

// ===========================================================================
// helpers
// ===========================================================================
__device__ __forceinline__ uint32_t smem_u32(const void* p) {
    uint32_t a;
    asm("{ .reg .u64 t; cvta.to.shared.u64 t, %1; cvt.u32.u64 %0, t; }" : "=r"(a) : "l"(p));
    return a;
}
__device__ __forceinline__ uint32_t swz(uint32_t off) {           // Swizzle<3,4,3>
    return off ^ ((off >> 3) & 0x70);
}
__device__ __forceinline__ unsigned int sortable_f32(float f) {
    unsigned int u = __float_as_uint(f);
    return (u & 0x80000000u) ? ~u : (u | 0x80000000u);
}

#define CP16(dst, src) \
    asm volatile("cp.async.ca.shared.global [%0], [%1], 16;" :: "r"(dst), "l"(src))
#define CP_COMMIT() asm volatile("cp.async.commit_group;" ::: "memory")
#define CP_WAIT0()  asm volatile("cp.async.wait_group 0;" ::: "memory")

__device__ __forceinline__ void ldsm_x4(uint32_t* r, uint32_t addr) {
    asm volatile("ldmatrix.sync.aligned.m8n8.x4.shared.b16 {%0,%1,%2,%3}, [%4];"
        : "=r"(r[0]), "=r"(r[1]), "=r"(r[2]), "=r"(r[3]) : "r"(addr));
}
__device__ __forceinline__ void mma_16816(float* d, const uint32_t* a,
                                          uint32_t b0, uint32_t b1) {
    asm volatile(
        "mma.sync.aligned.m16n8k16.row.col.f32.f16.f16.f32 "
        "{%0,%1,%2,%3}, {%4,%5,%6,%7}, {%8,%9}, {%0,%1,%2,%3};"
        : "+f"(d[0]), "+f"(d[1]), "+f"(d[2]), "+f"(d[3])
        : "r"(a[0]), "r"(a[1]), "r"(a[2]), "r"(a[3]), "r"(b0), "r"(b1));
}

// ===========================================================================
// init: zero hist2 + loss + rnorm2 + cmax (graph replays)
// ===========================================================================
__global__ void init_kernel() {
    int i = blockIdx.x * blockDim.x + threadIdx.x;   // grid 64 x 256 = 16384
    if (i < NT) g_rnorm2[i] = 0.0f;
    if (i < QQ * CC) g_hist2[i] = 0;
    if (i < QQ) { g_loss[i] = 0.0f; g_cmax2[i] = 0; }
}

// codebook prep: hi split, ||c||^2, per-stage max norm
__global__ void cbprep_kernel(const float* __restrict__ cb) {
    int code = blockIdx.x;             // 0..6143 (q*1024+c)
    int tid  = threadIdx.x;            // 128
    size_t base = (size_t)code * DD;
    float4 v = ((const float4*)(cb + base))[tid];

    __half2* hp = (__half2*)(g_cb_h + base + tid * 4);
    hp[0] = __halves2half2(__float2half(v.x), __float2half(v.y));
    hp[1] = __halves2half2(__float2half(v.z), __float2half(v.w));

    float s = v.x * v.x + v.y * v.y + v.z * v.z + v.w * v.w;
    #pragma unroll
    for (int off = 16; off > 0; off >>= 1) s += __shfl_down_sync(0xffffffffu, s, off);
    __shared__ float ws[4];
    if ((tid & 31) == 0) ws[tid >> 5] = s;
    __syncthreads();
    if (tid == 0) {
        float n = ws[0] + ws[1] + ws[2] + ws[3];
        g_cbnorm[code] = n;
        atomicMax(&g_cmax2[code >> 10], __float_as_int(n));  // norms > 0
    }
}

// transpose in: x (N, D, T) -> residual (NT, D) fp16 hi/lo; accumulate row norms
__global__ void transpose_in_kernel(const float* __restrict__ x) {
    __shared__ float tile[32][33];
    int n  = blockIdx.z;
    int t0 = blockIdx.x * 32;
    int d0 = blockIdx.y * 32;
    int tx = threadIdx.x, ty = threadIdx.y;  // (32, 8)

    #pragma unroll
    for (int i = 0; i < 4; i++) {
        int d = d0 + ty + i * 8;
        tile[ty + i * 8][tx] = x[(size_t)n * DD * TT + (size_t)d * TT + (t0 + tx)];
    }
    __syncthreads();
    #pragma unroll
    for (int i = 0; i < 4; i++) {
        int t = t0 + ty + i * 8;
        float v = tile[tx][ty + i * 8];
        size_t gi = (size_t)(n * TT + t) * DD + (d0 + tx);
        __half h = __float2half(v);
        g_res_h[gi] = h;
        g_res_l[gi] = __float2half(v - __half2float(h));
        float s = v * v;
        #pragma unroll
        for (int off = 16; off > 0; off >>= 1) s += __shfl_down_sync(0xffffffffu, s, off);
        if (tx == 0) atomicAdd(&g_rnorm2[n * TT + t], s);
    }
}

// ===========================================================================
// PASS 1: hh-only distance matrix, fp16 output, coalesced via smem staging
// in the dead compute buffer (round-13 proven config). Persistent grid,
// tile = 64 rows x 128 codes x K512, 128 threads = 4 warps (2m x 2n).
// ===========================================================================
#define MROWS   64
#define NCODES  128
#define KC      64
#define NCHUNK  (DD / KC)           // 8
#define NTILES  ((NT / MROWS) * (CC / NCODES))   // 2048
#define GRID_ARG 456

#define OFF_AH   0
#define OFF_BH   (8*1024)
#define BUF_BYTES (24*1024)
#define DSTRIDE  272                 // 64 rows x 272B staging (fits in 24KB buffer)
#define ARG_SMEM (2*BUF_BYTES)       // 49152

__global__ void __launch_bounds__(128) dist_kernel(int q) {
    extern __shared__ char smem[];
    const uint32_t sb = smem_u32(smem);
    const int tid  = threadIdx.x;
    const int lane = tid & 31;
    const int wid  = tid >> 5;
    const int wm   = wid & 1;          // 0..1  (32 rows each)
    const int wn   = wid >> 1;         // 0..1  (64 codes each)
    const int bid  = blockIdx.x;

    const __half* __restrict__ resh = g_res_h;
    const __half* __restrict__ cbh  = g_cb_h + (size_t)q * CC * DD;
    const float*  __restrict__ norms = g_cbnorm + q * CC;

    int ntiles = 0;
    for (int t = bid; t < NTILES; t += GRID_ARG) ntiles++;
    if (ntiles == 0) return;
    const int NG = ntiles * NCHUNK;

    float d[2][8][4];

    const int aRow  = (lane & 7) + ((lane >> 3) & 1) * 8;
    const int aK    = ((lane >> 4) & 1) * 8;
    const int bCode = (lane & 7) + ((lane >> 4) & 1) * 8;
    const int bK    = ((lane >> 3) & 1) * 8;

    auto issue = [&](int g) {
        const int t  = bid + GRID_ARG * (g >> 3);
        const int rb = (t & 255) * MROWS;
        const int ct = (t >> 8) * NCODES;
        const int k0 = (g & 7) * KC;
        const uint32_t bufb = sb + (g & 1) * BUF_BYTES;
        #pragma unroll
        for (int p = 0; p < 4; p++) {
            int seg = tid + p * 128;         // 0..511 (A: 64 rows x 8 segs)
            int row = seg >> 3, s8 = seg & 7;
            uint32_t so = swz((uint32_t)(row * 128 + s8 * 16));
            CP16(bufb + OFF_AH + so, resh + (size_t)(rb + row) * DD + k0 + s8 * 8);
        }
        #pragma unroll
        for (int p = 0; p < 8; p++) {
            int seg = tid + p * 128;         // 0..1023 (B: 128 codes x 8 segs)
            int row = seg >> 3, s8 = seg & 7;
            uint32_t so = swz((uint32_t)(row * 128 + s8 * 16));
            CP16(bufb + OFF_BH + so, cbh + (size_t)(ct + row) * DD + k0 + s8 * 8);
        }
        CP_COMMIT();
    };

    issue(0);
    for (int g = 0; g < NG; g++) {
        CP_WAIT0();
        __syncthreads();       // publish loads; also orders prior epilogue copy-reads

        if ((g & 7) == 0) {
            #pragma unroll
            for (int i = 0; i < 2; i++)
                #pragma unroll
                for (int j = 0; j < 8; j++)
                    #pragma unroll
                    for (int e = 0; e < 4; e++) d[i][j][e] = 0.0f;
        }

        if (g + 1 < NG) issue(g + 1);

        const uint32_t bufb = sb + (g & 1) * BUF_BYTES;
        #pragma unroll
        for (int kk = 0; kk < KC; kk += 16) {
            uint32_t ah[2][4];
            #pragma unroll
            for (int i = 0; i < 2; i++) {
                uint32_t so = swz((uint32_t)((wm * 32 + i * 16 + aRow) * 128 + (kk + aK) * 2));
                ldsm_x4(ah[i], bufb + OFF_AH + so);
            }
            #pragma unroll
            for (int j2 = 0; j2 < 4; j2++) {
                uint32_t bh[4];
                uint32_t so = swz((uint32_t)((wn * 64 + j2 * 16 + bCode) * 128 + (kk + bK) * 2));
                ldsm_x4(bh, bufb + OFF_BH + so);
                #pragma unroll
                for (int i = 0; i < 2; i++)
                    #pragma unroll
                    for (int h = 0; h < 2; h++)
                        mma_16816(d[i][j2 * 2 + h], ah[i], bh[h * 2], bh[h * 2 + 1]);
            }
        }

        // ---- tile epilogue: distances -> smem staging -> coalesced fp16 ----
        if ((g & 7) == 7) {
            const int t  = bid + GRID_ARG * (g >> 3);
            const int rb = (t & 255) * MROWS;
            const int ct = (t >> 8) * NCODES;
            char* stg = smem + (g & 1) * BUF_BYTES;   // dead until issue(g+2)

            // all warps must finish ldsm reads of this buffer before staging
            // overwrites it (cross-warp WAR).
            __syncthreads();

            #pragma unroll
            for (int i = 0; i < 2; i++)
                #pragma unroll
                for (int j = 0; j < 8; j++)
                    #pragma unroll
                    for (int e2 = 0; e2 < 2; e2++) {
                        int rowL = wm * 32 + i * 16 + (lane >> 2) + e2 * 8;
                        int colL = wn * 64 + j * 8 + 2 * (lane & 3);
                        float dx = __ldg(&norms[ct + colL])     - 2.0f * d[i][j][e2 * 2 + 0];
                        float dy = __ldg(&norms[ct + colL + 1]) - 2.0f * d[i][j][e2 * 2 + 1];
                        *(__half2*)(stg + rowL * DSTRIDE + colL * 2) =
                            __halves2half2(__float2half(dx), __float2half(dy));
                    }
            __syncthreads();
            // coalesced copy: 64 rows x 256B (16B per thread-seg)
            #pragma unroll
            for (int p = 0; p < 8; p++) {
                int seg = tid + p * 128;     // 0..1023
                int rowL = seg >> 4, c16 = seg & 15;
                uint4 v = *(uint4*)(stg + rowL * DSTRIDE + c16 * 16);
                *(uint4*)((char*)(g_dist + (size_t)(rb + rowL) * CC + ct) + c16 * 16) = v;
            }
            // next iteration's CP_WAIT0 + __syncthreads orders these reads
            // before issue(g+2) refills this buffer.
        }
    }
}

// ===========================================================================
// PASS 2 (warp-synchronous): one warp per row, 2 rows per warp.
// grid = 1024 blocks x 256 threads. No block barriers in the hot path.
// ===========================================================================
#define RWARPS 8
#define ROWS_PER_WARP 2
#define RBLOCKS (NT / (RWARPS * ROWS_PER_WARP))   // 1024

__global__ void __launch_bounds__(256) refine_update_kernel(const float* __restrict__ cb32, int q) {
    const int tid  = threadIdx.x;
    const int lane = tid & 31;
    const int wid  = tid >> 5;
    __shared__ float s_loss;
    if (tid == 0) s_loss = 0.0f;
    __syncthreads();

    const float* __restrict__ norms = g_cbnorm + q * CC;
    const float cmax = sqrtf(__int_as_float(g_cmax2[q]));

    #pragma unroll
    for (int r = 0; r < ROWS_PER_WARP; r++) {
        const int row = blockIdx.x * (RWARPS * ROWS_PER_WARP) + wid * ROWS_PER_WARP + r;

        // ---- load exact residual: a[2*j+e] <-> k = j*64 + lane*2 + e ----
        float a[16];
        const __half2* hr = (const __half2*)(g_res_h + (size_t)row * DD);
        const __half2* lr = (const __half2*)(g_res_l + (size_t)row * DD);
        #pragma unroll
        for (int j = 0; j < 8; j++) {
            __half2 h = hr[j * 32 + lane], l = lr[j * 32 + lane];
            a[2 * j]     = __low2float(h)  + __low2float(l);
            a[2 * j + 1] = __high2float(h) + __high2float(l);
        }

        // ---- load d_hh (32 values per lane) + lane argmin (ascending c) ----
        const __half2* drow = (const __half2*)(g_dist + (size_t)row * CC);
        __half2 dh[16];
        float bv = 3.4e38f; int bi = 0;
        #pragma unroll
        for (int it = 0; it < 16; it++) {
            dh[it] = drow[it * 32 + lane];
            float dx = __low2float(dh[it]), dy = __high2float(dh[it]);
            int c0 = (it * 32 + lane) * 2;
            if (dx < bv) { bv = dx; bi = c0; }
            if (dy < bv) { bv = dy; bi = c0 + 1; }
        }
        unsigned long long key =
            ((unsigned long long)sortable_f32(bv) << 32) | (unsigned)bi;
        #pragma unroll
        for (int off = 16; off > 0; off >>= 1) {
            unsigned long long o = __shfl_xor_sync(0xffffffffu, key, off);
            if (o < key) key = o;
        }
        unsigned u = (unsigned)(key >> 32);
        float dmin = __uint_as_float((u & 0x80000000u) ? (u & 0x7FFFFFFFu) : ~u);

        // margin (pairwise fp16 dot bound + fp16 storage quantization)
        float eps = sqrtf(g_rnorm2[row]) * cmax * (1.0f / 128.0f) + 1.0f;
        float T = dmin + eps;

        // ---- count candidates ----
        int ncand = 0;
        #pragma unroll
        for (int it = 0; it < 16; it++) {
            float dx = __low2float(dh[it]), dy = __high2float(dh[it]);
            ncand += __popc(__ballot_sync(0xffffffffu, dx <= T));
            ncand += __popc(__ballot_sync(0xffffffffu, dy <= T));
        }

        int bc;
        if (ncand == 1) {
            bc = (int)(unsigned)(key & 0xFFFFFFFFull);   // unique candidate = hh-argmin
        } else {
            // exact fp32 refinement over candidates (order-independent tie-break)
            float bd = 3.4e38f; bc = CC;
            #pragma unroll 4
            for (int it = 0; it < 16; it++) {
                float dx = __low2float(dh[it]), dy = __high2float(dh[it]);
                #pragma unroll
                for (int e = 0; e < 2; e++) {
                    unsigned mask = __ballot_sync(0xffffffffu, (e ? dy : dx) <= T);
                    while (mask) {
                        int src = __ffs(mask) - 1; mask &= mask - 1;
                        int c = (it * 32 + src) * 2 + e;
                        const float* crow = cb32 + (size_t)c * DD;
                        float p = 0.0f;
                        #pragma unroll
                        for (int j = 0; j < 8; j++) {
                            float2 cv = *(const float2*)(crow + j * 64 + lane * 2);
                            p += a[2 * j] * cv.x + a[2 * j + 1] * cv.y;
                        }
                        #pragma unroll
                        for (int off = 16; off > 0; off >>= 1)
                            p += __shfl_xor_sync(0xffffffffu, p, off);
                        float dd = norms[c] - 2.0f * p;
                        if (dd < bd || (dd == bd && c < bc)) { bd = dd; bc = c; }
                    }
                }
            }
        }

        if (lane == 0) {
            g_indices[row * QQ + q] = bc;
            atomicAdd(&g_hist2[q * CC + bc], 1);
        }

        // ---- residual update + loss + forward row norm ----
        const float* crow = cb32 + (size_t)bc * DD;
        __half2* hw = (__half2*)(g_res_h + (size_t)row * DD);
        __half2* lw = (__half2*)(g_res_l + (size_t)row * DD);
        float lsum = 0.0f;
        #pragma unroll
        for (int j = 0; j < 8; j++) {
            float2 cv = *(const float2*)(crow + j * 64 + lane * 2);
            float r0 = a[2 * j] - cv.x;
            float r1 = a[2 * j + 1] - cv.y;
            __half h0 = __float2half(r0), h1 = __float2half(r1);
            hw[j * 32 + lane] = __halves2half2(h0, h1);
            lw[j * 32 + lane] = __halves2half2(__float2half(r0 - __half2float(h0)),
                                               __float2half(r1 - __half2float(h1)));
            lsum += r0 * r0 + r1 * r1;
        }
        #pragma unroll
        for (int off = 16; off > 0; off >>= 1)
            lsum += __shfl_xor_sync(0xffffffffu, lsum, off);
        if (lane == 0) {
            g_rnorm2[row] = lsum;
            atomicAdd(&s_loss, lsum);
        }
    }

    __syncthreads();
    if (tid == 0) atomicAdd(&g_loss[q], s_loss);
}

// ---------------------------------------------------------------------------
// output: quantized_out (N,D,T) = x - residual_final  (transpose back)
// ---------------------------------------------------------------------------
__global__ void transpose_out_kernel(const float* __restrict__ x, float* __restrict__ out) {
    __shared__ float tile[32][33];
    int n  = blockIdx.z;
    int t0 = blockIdx.x * 32;
    int d0 = blockIdx.y * 32;
    int tx = threadIdx.x, ty = threadIdx.y;  // (32, 8)

    #pragma unroll
    for (int i = 0; i < 4; i++) {
        int t = t0 + ty + i * 8;
        size_t gi = (size_t)(n * TT + t) * DD + (d0 + tx);
        tile[ty + i * 8][tx] = __half2float(g_res_h[gi]) + __half2float(g_res_l[gi]);
    }
    __syncthreads();
    #pragma unroll
    for (int i = 0; i < 4; i++) {
        int d = d0 + ty + i * 8;
        size_t gi = (size_t)n * DD * TT + (size_t)d * TT + (t0 + tx);
        out[gi] = x[gi] - tile[tx][ty + i * 8];
    }
}

__global__ void idx_kernel(float* __restrict__ out) {
    int i = blockIdx.x * blockDim.x + threadIdx.x;
    if (i < OUT_IDX) out[OUT_QUANT + i] = (float)g_indices[i];
}

// all 6 perplexities + mean loss
__global__ void finalize_kernel(float* __restrict__ out) {
    int tid = threadIdx.x;   // 256
    __shared__ float ws[8];
    __shared__ float perp_sum;
    if (tid == 0) perp_sum = 0.0f;
    __syncthreads();

    for (int q = 0; q < QQ; q++) {
        float s = 0.0f;
        for (int i = tid; i < CC; i += 256) {
            float p = (float)g_hist2[q * CC + i] * (1.0f / (float)NT);
            s += p * logf(p + 1e-10f);
        }
        #pragma unroll
        for (int off = 16; off > 0; off >>= 1) s += __shfl_down_sync(0xffffffffu, s, off);
        if ((tid & 31) == 0) ws[tid >> 5] = s;
        __syncthreads();
        if (tid == 0) {
            float t = 0.0f;
            #pragma unroll
            for (int i = 0; i < 8; i++) t += ws[i];
            perp_sum += expf(-t);
        }
        __syncthreads();
    }

    if (tid == 0) {
        float l = 0.0f;
        #pragma unroll
        for (int q = 0; q < QQ; q++) l += g_loss[q];
        out[OUT_QUANT + OUT_IDX + 0] = l / ((float)NT * (float)DD) / (float)QQ;
        out[OUT_QUANT + OUT_IDX + 1] = perp_sum / (float)QQ;
    }
}

// ---------------------------------------------------------------------------
extern "C" void kernel_launch(void* const* d_in, const int* in_sizes, int n_in,
                              void* d_out, int out_size) {
    const float* x  = (const float*)d_in[0];   // (64, 512, 256) fp32
    const float* cb = (const float*)d_in[1];   // (6, 1024, 512) fp32
    float* out = (float*)d_out;

    static bool attr_set = false;
    if (!attr_set) {
        cudaFuncSetAttribute(dist_kernel,
                             cudaFuncAttributeMaxDynamicSharedMemorySize, ARG_SMEM);
        attr_set = true;
    }

    init_kernel<<<64, 256>>>();

    dim3 tb(32, 8);
    dim3 tg(TT / 32, DD / 32, NN);   // (8, 16, 64)
    transpose_in_kernel<<<tg, tb>>>(x);

    cbprep_kernel<<<QQ * CC, 128>>>(cb);

    for (int q = 0; q < QQ; q++) {
        const float* cbq = cb + (size_t)q * CC * DD;
        dist_kernel<<<GRID_ARG, 128, ARG_SMEM>>>(q);
        refine_update_kernel<<<RBLOCKS, 256>>>(cbq, q);
    }

    transpose_out_kernel<<<tg, tb>>>(x, out);
    idx_kernel<<<(OUT_IDX + 255) / 256, 256>>>(out);
    finalize_kernel<<<1, 256>>>(out);
}